// round 12
// baseline (speedup 1.0000x reference)
#include <cuda_runtime.h>
#include <cuda_bf16.h>
#include <math.h>
#include <stdint.h>

// Problem dims (fixed by reference)
#define BATCH   64          // B*L
#define NNODE   4096        // H
#define NFEAT   128         // W == nclass
#define NHID    256

// ---------------------------------------------------------------------------
// Static device scratch (no allocations allowed)
// ---------------------------------------------------------------------------
__device__ int8_t g_A1 [(size_t)NNODE * NNODE];                  // adj level-1
__device__ int8_t g_A2q[(size_t)NNODE * NNODE];                  // adj level-2
__device__ int8_t g_B1 [(size_t)BATCH * NFEAT * NNODE];          // B level-1 [b][w][k]
__device__ int8_t g_B2q[(size_t)BATCH * NFEAT * NNODE];          // B level-2
__device__ float  g_T  [(size_t)BATCH * NNODE * NFEAT];          // GEMM1 out
__device__ float  g_A2T[(size_t)BATCH * NFEAT * NNODE];          // MLP out transposed
__device__ unsigned g_scal[3];                                   // absmax: adj, x, mlp
__device__ __nv_bfloat16 g_W1Th[NHID * NFEAT];                   // W1^T hi [256][128]
__device__ __nv_bfloat16 g_W1Tl[NHID * NFEAT];                   // W1^T lo
__device__ __nv_bfloat16 g_W2Th[NFEAT * NHID];                   // W2^T hi [128][256]
__device__ __nv_bfloat16 g_W2Tl[NFEAT * NHID];                   // W2^T lo

// ---------------------------------------------------------------------------
// PTX helpers (sm_80-era: ldmatrix / mma.sync / cp.async)
// ---------------------------------------------------------------------------
__device__ __forceinline__ uint32_t smem_u32(const void* p) {
    uint32_t a;
    asm("{ .reg .u64 t; cvta.to.shared.u64 t, %1; cvt.u32.u64 %0, t; }" : "=r"(a) : "l"(p));
    return a;
}

#define LDSM4(r, a)                                                                 \
    asm volatile("ldmatrix.sync.aligned.m8n8.x4.shared.b16 {%0,%1,%2,%3}, [%4];"    \
        : "=r"((r)[0]), "=r"((r)[1]), "=r"((r)[2]), "=r"((r)[3]) : "r"(a))

#define LDSM2(r, a)                                                                 \
    asm volatile("ldmatrix.sync.aligned.m8n8.x2.shared.b16 {%0,%1}, [%2];"          \
        : "=r"((r)[0]), "=r"((r)[1]) : "r"(a))

#define MMA_S8(c, a, bb)                                                            \
    asm volatile("mma.sync.aligned.m16n8k32.row.col.s32.s8.s8.s32 "                 \
        "{%0,%1,%2,%3}, {%4,%5,%6,%7}, {%8,%9}, {%0,%1,%2,%3};"                     \
        : "+r"((c)[0]), "+r"((c)[1]), "+r"((c)[2]), "+r"((c)[3])                    \
        : "r"((a)[0]), "r"((a)[1]), "r"((a)[2]), "r"((a)[3]),                       \
          "r"((bb)[0]), "r"((bb)[1]))

#define MMA_BF16(c, a, bb)                                                          \
    asm volatile("mma.sync.aligned.m16n8k16.row.col.f32.bf16.bf16.f32 "             \
        "{%0,%1,%2,%3}, {%4,%5,%6,%7}, {%8,%9}, {%0,%1,%2,%3};"                     \
        : "+f"((c)[0]), "+f"((c)[1]), "+f"((c)[2]), "+f"((c)[3])                    \
        : "r"((a)[0]), "r"((a)[1]), "r"((a)[2]), "r"((a)[3]),                       \
          "r"((bb)[0]), "r"((bb)[1]))

#define CP16(dst, src) asm volatile("cp.async.cg.shared.global [%0], [%1], 16;" :: "r"(dst), "l"(src) : "memory")
#define CP_COMMIT()    asm volatile("cp.async.commit_group;" ::: "memory")
#define CP_WAIT1()     asm volatile("cp.async.wait_group 1;" ::: "memory")
#define CP_WAIT0()     asm volatile("cp.async.wait_group 0;" ::: "memory")

// two-level symmetric quantization: v ~= (max/127) * (q1 + q2/256)
__device__ __forceinline__ void q2lvl(float v, float inv, int& o1, int& o2) {
    float q  = v * inv;
    float r1 = rintf(q);
    r1 = fminf(127.f, fmaxf(-127.f, r1));
    float r2 = rintf((q - r1) * 256.f);
    r2 = fminf(127.f, fmaxf(-127.f, r2));
    o1 = (int)r1; o2 = (int)r2;
}

__device__ __forceinline__ void bf16split(float v, unsigned short& h, unsigned short& l) {
    __nv_bfloat16 hb = __float2bfloat16_rn(v);
    h = __bfloat16_as_ushort(hb);
    l = __bfloat16_as_ushort(__float2bfloat16_rn(v - __bfloat162float(hb)));
}

// ---------------------------------------------------------------------------
// tiny kernels
// ---------------------------------------------------------------------------
__global__ void zero_scal(unsigned* s) { s[0] = 0u; s[1] = 0u; s[2] = 0u; }

__global__ void __launch_bounds__(256)
rmax4(const float4* __restrict__ p, int n4, unsigned* out)
{
    float m = 0.f;
    for (int i = blockIdx.x * blockDim.x + threadIdx.x; i < n4; i += gridDim.x * blockDim.x) {
        float4 v = p[i];
        m = fmaxf(m, fmaxf(fmaxf(fabsf(v.x), fabsf(v.y)), fmaxf(fabsf(v.z), fabsf(v.w))));
    }
    #pragma unroll
    for (int o = 16; o > 0; o >>= 1) m = fmaxf(m, __shfl_xor_sync(0xFFFFFFFFu, m, o));
    __shared__ float red[8];
    if ((threadIdx.x & 31) == 0) red[threadIdx.x >> 5] = m;
    __syncthreads();
    if (threadIdx.x == 0) {
        float b = red[0];
        #pragma unroll
        for (int i = 1; i < 8; i++) b = fmaxf(b, red[i]);
        atomicMax(out, __float_as_uint(b));
    }
}

// weight transpose + bf16 split preps
__global__ void __launch_bounds__(256)
wprep1(const float* __restrict__ W1, __nv_bfloat16* __restrict__ h, __nv_bfloat16* __restrict__ l)
{
    int gid = blockIdx.x * 256 + threadIdx.x;           // 32768
    int r = gid >> 7, c = gid & 127;                    // out [256][128]
    unsigned short hh, ll;
    bf16split(W1[(size_t)c * NHID + r], hh, ll);
    h[gid] = __ushort_as_bfloat16(hh);
    l[gid] = __ushort_as_bfloat16(ll);
}
__global__ void __launch_bounds__(256)
wprep2(const float* __restrict__ W2, __nv_bfloat16* __restrict__ h, __nv_bfloat16* __restrict__ l)
{
    int gid = blockIdx.x * 256 + threadIdx.x;           // 32768
    int r = gid >> 8, c = gid & 255;                    // out [128][256]
    unsigned short hh, ll;
    bf16split(W2[(size_t)c * NFEAT + r], hh, ll);
    h[gid] = __ushort_as_bfloat16(hh);
    l[gid] = __ushort_as_bfloat16(ll);
}

// ---------------------------------------------------------------------------
// pointwise 2-level quantize
// ---------------------------------------------------------------------------
__global__ void __launch_bounds__(256)
quant_pt(const float* __restrict__ src, int8_t* __restrict__ d1,
         int8_t* __restrict__ d2, const unsigned* __restrict__ mx)
{
    const float inv = 127.f / fmaxf(__uint_as_float(*mx), 1e-30f);
    const size_t i = ((size_t)blockIdx.x * 256 + threadIdx.x) * 4;
    float4 v = *(const float4*)(src + i);
    int a1, a2, b1, b2, c1, c2, e1, e2;
    q2lvl(v.x, inv, a1, a2); q2lvl(v.y, inv, b1, b2);
    q2lvl(v.z, inv, c1, c2); q2lvl(v.w, inv, e1, e2);
    *(char4*)(d1 + i) = make_char4((char)a1, (char)b1, (char)c1, (char)e1);
    *(char4*)(d2 + i) = make_char4((char)a2, (char)b2, (char)c2, (char)e2);
}

// ---------------------------------------------------------------------------
// x [b][n][w] fp32 -> int8x2 transposed [b][w][n]
// ---------------------------------------------------------------------------
__global__ void __launch_bounds__(256)
quant_xT(const float* __restrict__ x, int8_t* __restrict__ d1,
         int8_t* __restrict__ d2, const unsigned* __restrict__ mx)
{
    __shared__ float t[32][33];
    const float inv = 127.f / fmaxf(__uint_as_float(*mx), 1e-30f);
    const int tx = threadIdx.x, ty = threadIdx.y;       // 32 x 8
    const int n0 = blockIdx.x * 32, w0 = blockIdx.y * 32, b = blockIdx.z;
    #pragma unroll
    for (int j = 0; j < 4; j++) {
        int n = n0 + ty + j * 8;
        t[ty + j * 8][tx] = x[((size_t)b * NNODE + n) * NFEAT + w0 + tx];
    }
    __syncthreads();
    #pragma unroll
    for (int j = 0; j < 4; j++) {
        int w = w0 + ty + j * 8;
        int q1, q2;
        q2lvl(t[tx][ty + j * 8], inv, q1, q2);
        size_t o = ((size_t)b * NFEAT + w) * NNODE + n0 + tx;
        d1[o] = (int8_t)q1; d2[o] = (int8_t)q2;
    }
}

// ---------------------------------------------------------------------------
// int8 two-level GEMM: C[b][n][w] = sum_k adj[n][k] * X[b][k][w]
// 512 threads, 16 warps in 4(m) x 4(n) grid, warp tile 32x32 (R12: was 256thr
// 64x32 — doubles warps/SMSP for latency hiding; accumulators halve to fit).
// If out2 != null: fused epilogue out2 = log_softmax(C + bias2) (GEMM2 mode).
// ---------------------------------------------------------------------------
#define KC       128
#define NSTAGE   (NNODE / KC)              // 32
#define ROW_B    144
#define TILE_B   (128 * ROW_B)             // 18432
#define STAGE_B  (4 * TILE_B)              // 73728
#define SM_TOTAL (2 * STAGE_B)             // 147456

__global__ void __launch_bounds__(512, 1)
gemm_s8(const int8_t* __restrict__ A1, const int8_t* __restrict__ A2q,
        const int8_t* __restrict__ B1, const int8_t* __restrict__ B2q,
        float* __restrict__ C,
        const unsigned* __restrict__ maxA, const unsigned* __restrict__ maxB,
        float* __restrict__ out2, const float* __restrict__ bias2)
{
    extern __shared__ __align__(16) char smem[];
    const uint32_t sb = smem_u32(smem);
    const int tid  = threadIdx.x;
    const int wid  = tid >> 5, lane = tid & 31;
    const int wm   = wid & 3;              // 32-row m group
    const int wn   = wid >> 2;             // 32-col n group
    const int n0 = blockIdx.x * 128, b = blockIdx.y;

    const int8_t* tb[4] = {
        A1  + (size_t)n0 * NNODE, A2q + (size_t)n0 * NNODE,
        B1  + (size_t)b * NFEAT * NNODE, B2q + (size_t)b * NFEAT * NNODE };

    // cp.async plan: 4096 chunks(16B) / 512 threads = 8 per thread.
    // chunk c = j*512 + tid: tile = j>>1, row = (j&1)*64 + (tid>>3), col16 = tid&7.
    const int c16   = (tid & 7) * 16;
    const int rbase = tid >> 3;            // 0..63

    const uint32_t offA = (uint32_t)(wm * 32 + (lane & 15)) * ROW_B + (lane >> 4) * 16;
    const uint32_t offB = (uint32_t)(wn * 32 + (lane & 7)) * ROW_B + ((lane >> 3) & 1) * 16;

    int p1[2][4][4], p2[2][4][4];
    #pragma unroll
    for (int mi = 0; mi < 2; mi++)
        #pragma unroll
        for (int ni = 0; ni < 4; ni++)
            #pragma unroll
            for (int e = 0; e < 4; e++) { p1[mi][ni][e] = 0; p2[mi][ni][e] = 0; }

    #pragma unroll
    for (int j = 0; j < 8; j++) {
        const int row = (j & 1) * 64 + rbase;
        CP16(sb + (j >> 1) * TILE_B + row * ROW_B + c16,
             tb[j >> 1] + (size_t)row * NNODE + c16);
    }
    CP_COMMIT();

    for (int i = 0; i < NSTAGE; i++) {
        const int buf = i & 1;
        if (i < NSTAGE - 1) {
            const uint32_t dbase = sb + (buf ^ 1) * STAGE_B;
            const int koff = (i + 1) * KC;
            #pragma unroll
            for (int j = 0; j < 8; j++) {
                const int row = (j & 1) * 64 + rbase;
                CP16(dbase + (j >> 1) * TILE_B + row * ROW_B + c16,
                     tb[j >> 1] + (size_t)row * NNODE + koff + c16);
            }
            CP_COMMIT();
            CP_WAIT1();
        } else {
            CP_WAIT0();
        }
        __syncthreads();

        const uint32_t s = sb + buf * STAGE_B;
        #pragma unroll
        for (int ks = 0; ks < 4; ks++) {
            uint32_t a1f[2][4], a2f[2][4];
            #pragma unroll
            for (int mi = 0; mi < 2; mi++) {
                const uint32_t a = s + offA + mi * (16 * ROW_B) + ks * 32;
                LDSM4(a1f[mi], a);
                LDSM4(a2f[mi], a + TILE_B);
            }
            #pragma unroll
            for (int ni = 0; ni < 4; ni++) {
                uint32_t b1f[2], b2f[2];
                const uint32_t a = s + 2 * TILE_B + offB + ni * (8 * ROW_B) + ks * 32;
                LDSM2(b1f, a);
                LDSM2(b2f, a + TILE_B);
                #pragma unroll
                for (int mi = 0; mi < 2; mi++) {
                    MMA_S8(p1[mi][ni], a1f[mi], b1f);
                    MMA_S8(p2[mi][ni], a1f[mi], b2f);
                    MMA_S8(p2[mi][ni], a2f[mi], b1f);
                }
            }
        }
        __syncthreads();
    }

    const float mA = __uint_as_float(*maxA), mB = __uint_as_float(*maxB);
    const float s1 = (mA * mB) * (1.f / 16129.f);   // /127^2
    const float s2 = s1 * (1.f / 256.f);
    const int mrow = wm * 32 + (lane >> 2);
    const int ncol = wn * 32 + (lane & 3) * 2;

    if (out2 == nullptr) {
        float* Cb = C + ((size_t)b * NNODE + n0) * NFEAT;
        #pragma unroll
        for (int mi = 0; mi < 2; mi++) {
            #pragma unroll
            for (int ni = 0; ni < 4; ni++) {
                float* q0 = Cb + (size_t)(mrow + mi * 16) * NFEAT + ncol + ni * 8;
                float* q1 = q0 + 8 * NFEAT;
                *(float2*)q0 = make_float2(s1 * (float)p1[mi][ni][0] + s2 * (float)p2[mi][ni][0],
                                           s1 * (float)p1[mi][ni][1] + s2 * (float)p2[mi][ni][1]);
                *(float2*)q1 = make_float2(s1 * (float)p1[mi][ni][2] + s2 * (float)p2[mi][ni][2],
                                           s1 * (float)p1[mi][ni][3] + s2 * (float)p2[mi][ni][3]);
            }
        }
    } else {
        // fused bias + log_softmax epilogue: bounce acc through smem (stages dead)
        float* sm = (float*)smem;                       // [128][132] fp32
        #pragma unroll
        for (int mi = 0; mi < 2; mi++) {
            #pragma unroll
            for (int ni = 0; ni < 4; ni++) {
                const int r0 = mrow + mi * 16, c0 = ncol + ni * 8;
                sm[r0 * 132 + c0]           = s1 * (float)p1[mi][ni][0] + s2 * (float)p2[mi][ni][0];
                sm[r0 * 132 + c0 + 1]       = s1 * (float)p1[mi][ni][1] + s2 * (float)p2[mi][ni][1];
                sm[(r0 + 8) * 132 + c0]     = s1 * (float)p1[mi][ni][2] + s2 * (float)p2[mi][ni][2];
                sm[(r0 + 8) * 132 + c0 + 1] = s1 * (float)p1[mi][ni][3] + s2 * (float)p2[mi][ni][3];
            }
        }
        __syncthreads();
        const float4 bb = ((const float4*)bias2)[lane];
        for (int rr = wid * 8; rr < wid * 8 + 8; rr++) {
            float4 v = *(float4*)&sm[rr * 132 + lane * 4];
            float v0 = v.x + bb.x, v1 = v.y + bb.y, v2 = v.z + bb.z, v3 = v.w + bb.w;
            float m = fmaxf(fmaxf(v0, v1), fmaxf(v2, v3));
            #pragma unroll
            for (int o = 16; o > 0; o >>= 1) m = fmaxf(m, __shfl_xor_sync(0xFFFFFFFFu, m, o));
            float ss = expf(v0 - m) + expf(v1 - m) + expf(v2 - m) + expf(v3 - m);
            #pragma unroll
            for (int o = 16; o > 0; o >>= 1) ss += __shfl_xor_sync(0xFFFFFFFFu, ss, o);
            const float lse = m + logf(ss);
            float4 o4; o4.x = v0 - lse; o4.y = v1 - lse; o4.z = v2 - lse; o4.w = v3 - lse;
            *(float4*)(out2 + ((size_t)b * NNODE + n0 + rr) * NFEAT + lane * 4) = o4;
        }
    }
}

// ---------------------------------------------------------------------------
// MLP on tensor cores (bf16 3-term split both layers) — unchanged from R11.
// Per CTA: 128 rows. A2T[b][w][n] = relu(T @ W1 + b1) @ W2, + global absmax.
// ---------------------------------------------------------------------------
#define MROWB 272                                      // 256B data + 16 pad
#define MLVL  (128 * MROWB)                            // 34816
#define M_RA  0
#define M_RB  (2 * MLVL)                               // 69632
#define M_RC  (4 * MLVL)                               // 139264
#define M_SM  (6 * MLVL)                               // 208896

__global__ void __launch_bounds__(256, 1)
mlp_tensor(const float* __restrict__ T,
           const __nv_bfloat16* __restrict__ W1Th, const __nv_bfloat16* __restrict__ W1Tl,
           const __nv_bfloat16* __restrict__ W2Th, const __nv_bfloat16* __restrict__ W2Tl,
           const float* __restrict__ b1,
           float* __restrict__ A2T, unsigned* __restrict__ mx)
{
    extern __shared__ __align__(16) char smem[];
    const uint32_t sb = smem_u32(smem);
    const int tid  = threadIdx.x;
    const int wid  = tid >> 5, lane = tid & 31;
    const int wm   = wid & 1, wn = wid >> 1;
    const size_t row0 = (size_t)blockIdx.x * 128;
    const int b     = (int)(row0 >> 12);
    const int nbase = (int)(row0 & 4095);

    // --- issue W1T half0 loads, then convert T while they fly ---
    {
        #pragma unroll
        for (int j = 0; j < 8; j++) {
            int cid = j * 256 + tid;         // 2048
            int r = cid >> 4, c = cid & 15;
            CP16(sb + M_RB + r * MROWB + c * 16,        W1Th + (size_t)r * NFEAT + c * 8);
            CP16(sb + M_RB + MLVL + r * MROWB + c * 16, W1Tl + (size_t)r * NFEAT + c * 8);
        }
        CP_COMMIT();
    }
    {
        const int r  = tid >> 1;
        const int wb = (tid & 1) * 64;
        const float* src = T + (row0 + r) * NFEAT + wb;
        #pragma unroll
        for (int i = 0; i < 16; i++) {
            float4 v = *(const float4*)(src + i * 4);
            unsigned short h0,l0,h1,l1,h2,l2,h3,l3;
            bf16split(v.x, h0, l0); bf16split(v.y, h1, l1);
            bf16split(v.z, h2, l2); bf16split(v.w, h3, l3);
            uint32_t hi01 = (uint32_t)h0 | ((uint32_t)h1 << 16);
            uint32_t hi23 = (uint32_t)h2 | ((uint32_t)h3 << 16);
            uint32_t lo01 = (uint32_t)l0 | ((uint32_t)l1 << 16);
            uint32_t lo23 = (uint32_t)l2 | ((uint32_t)l3 << 16);
            const uint32_t base = sb + M_RA + r * MROWB + (wb + i * 4) * 2;
            asm volatile("st.shared.u32 [%0], %1;" :: "r"(base),     "r"(hi01));
            asm volatile("st.shared.u32 [%0], %1;" :: "r"(base + 4), "r"(hi23));
            asm volatile("st.shared.u32 [%0], %1;" :: "r"(base + MLVL),     "r"(lo01));
            asm volatile("st.shared.u32 [%0], %1;" :: "r"(base + MLVL + 4), "r"(lo23));
        }
    }
    CP_WAIT0();
    __syncthreads();

    const uint32_t offA = (uint32_t)(wm * 64 + (lane & 15)) * MROWB + (lane >> 4) * 16;
    const uint32_t offB = (uint32_t)(wn * 32 + (lane & 7)) * MROWB + ((lane >> 3) & 1) * 16;

    float acc2[4][4][4];
    #pragma unroll
    for (int mi = 0; mi < 4; mi++)
        #pragma unroll
        for (int ni = 0; ni < 4; ni++)
            #pragma unroll
            for (int e = 0; e < 4; e++) acc2[mi][ni][e] = 0.f;

    #pragma unroll 1
    for (int half = 0; half < 2; half++) {
        // ---- layer 1 half: h[:, half*128 .. half*128+127] = T @ W1T-half ----
        float acc1[4][4][4];
        #pragma unroll
        for (int mi = 0; mi < 4; mi++)
            #pragma unroll
            for (int ni = 0; ni < 4; ni++)
                #pragma unroll
                for (int e = 0; e < 4; e++) acc1[mi][ni][e] = 0.f;

        #pragma unroll
        for (int ks = 0; ks < 8; ks++) {
            uint32_t ah[4][4], al[4][4];
            #pragma unroll
            for (int mi = 0; mi < 4; mi++) {
                const uint32_t a = sb + M_RA + offA + mi * (16 * MROWB) + ks * 32;
                LDSM4(ah[mi], a);
                LDSM4(al[mi], a + MLVL);
            }
            #pragma unroll
            for (int ni = 0; ni < 4; ni++) {
                uint32_t bh[2], bl[2];
                const uint32_t a = sb + M_RB + offB + ni * (8 * MROWB) + ks * 32;
                LDSM2(bh, a);
                LDSM2(bl, a + MLVL);
                #pragma unroll
                for (int mi = 0; mi < 4; mi++) {
                    MMA_BF16(acc1[mi][ni], ah[mi], bh);
                    MMA_BF16(acc1[mi][ni], ah[mi], bl);
                    MMA_BF16(acc1[mi][ni], al[mi], bh);
                }
            }
        }
        __syncthreads();                     // everyone done reading RB

        // load W2T half into RB
        #pragma unroll
        for (int j = 0; j < 8; j++) {
            int cid = j * 256 + tid;
            int r = cid >> 4, c = cid & 15;
            CP16(sb + M_RB + r * MROWB + c * 16,
                 W2Th + (size_t)r * NHID + half * 128 + c * 8);
            CP16(sb + M_RB + MLVL + r * MROWB + c * 16,
                 W2Tl + (size_t)r * NHID + half * 128 + c * 8);
        }
        CP_COMMIT();

        // relu + bias + bf16 split h -> RC (overlaps with W2T copy)
        {
            const int cb = wn * 32 + (lane & 3) * 2;
            #pragma unroll
            for (int ni = 0; ni < 4; ni++) {
                const float2 bv = *(const float2*)(b1 + half * 128 + cb + ni * 8);
                #pragma unroll
                for (int mi = 0; mi < 4; mi++) {
                    const int r = wm * 64 + (lane >> 2) + mi * 16;
                    float h0 = fmaxf(acc1[mi][ni][0] + bv.x, 0.f);
                    float h1 = fmaxf(acc1[mi][ni][1] + bv.y, 0.f);
                    float h2 = fmaxf(acc1[mi][ni][2] + bv.x, 0.f);
                    float h3 = fmaxf(acc1[mi][ni][3] + bv.y, 0.f);
                    unsigned short a0,a1,a2,a3,b0,bb1,b2q,b3;
                    bf16split(h0, a0, b0); bf16split(h1, a1, bb1);
                    bf16split(h2, a2, b2q); bf16split(h3, a3, b3);
                    const uint32_t c2 = (cb + ni * 8) * 2;
                    uint32_t ad0 = sb + M_RC + r * MROWB + c2;
                    uint32_t ad1 = sb + M_RC + (r + 8) * MROWB + c2;
                    uint32_t hi0 = (uint32_t)a0 | ((uint32_t)a1 << 16);
                    uint32_t hi1 = (uint32_t)a2 | ((uint32_t)a3 << 16);
                    uint32_t lo0 = (uint32_t)b0 | ((uint32_t)bb1 << 16);
                    uint32_t lo1 = (uint32_t)b2q | ((uint32_t)b3 << 16);
                    asm volatile("st.shared.u32 [%0], %1;" :: "r"(ad0), "r"(hi0));
                    asm volatile("st.shared.u32 [%0], %1;" :: "r"(ad1), "r"(hi1));
                    asm volatile("st.shared.u32 [%0], %1;" :: "r"(ad0 + MLVL), "r"(lo0));
                    asm volatile("st.shared.u32 [%0], %1;" :: "r"(ad1 + MLVL), "r"(lo1));
                }
            }
        }
        CP_WAIT0();
        __syncthreads();                     // h + W2T half ready

        // ---- layer 2 half: acc2 += h_half @ W2T-half ----
        #pragma unroll
        for (int ks = 0; ks < 8; ks++) {
            uint32_t ah[4][4], al[4][4];
            #pragma unroll
            for (int mi = 0; mi < 4; mi++) {
                const uint32_t a = sb + M_RC + offA + mi * (16 * MROWB) + ks * 32;
                LDSM4(ah[mi], a);
                LDSM4(al[mi], a + MLVL);
            }
            #pragma unroll
            for (int ni = 0; ni < 4; ni++) {
                uint32_t bh[2], bl[2];
                const uint32_t a = sb + M_RB + offB + ni * (8 * MROWB) + ks * 32;
                LDSM2(bh, a);
                LDSM2(bl, a + MLVL);
                #pragma unroll
                for (int mi = 0; mi < 4; mi++) {
                    MMA_BF16(acc2[mi][ni], ah[mi], bh);
                    MMA_BF16(acc2[mi][ni], ah[mi], bl);
                    MMA_BF16(acc2[mi][ni], al[mi], bh);
                }
            }
        }
        if (half == 0) {
            __syncthreads();                 // done reading RB; reload W1T half1
            #pragma unroll
            for (int j = 0; j < 8; j++) {
                int cid = j * 256 + tid;
                int r = cid >> 4, c = cid & 15;
                CP16(sb + M_RB + r * MROWB + c * 16,
                     W1Th + (size_t)(128 + r) * NFEAT + c * 8);
                CP16(sb + M_RB + MLVL + r * MROWB + c * 16,
                     W1Tl + (size_t)(128 + r) * NFEAT + c * 8);
            }
            CP_COMMIT();
            CP_WAIT0();
            __syncthreads();
        }
    }

    // ---- epilogue: transpose via smem (RA/RB dead), write A2T + absmax ----
    __syncthreads();
    float* sm = (float*)smem;                // [128][132] fp32 in RA+RB space
    {
        const int mrow = wm * 64 + (lane >> 2);
        const int ncol = wn * 32 + (lane & 3) * 2;
        #pragma unroll
        for (int mi = 0; mi < 4; mi++)
            #pragma unroll
            for (int ni = 0; ni < 4; ni++) {
                const int r0 = mrow + mi * 16, c0 = ncol + ni * 8;
                sm[r0 * 132 + c0]           = acc2[mi][ni][0];
                sm[r0 * 132 + c0 + 1]       = acc2[mi][ni][1];
                sm[(r0 + 8) * 132 + c0]     = acc2[mi][ni][2];
                sm[(r0 + 8) * 132 + c0 + 1] = acc2[mi][ni][3];
            }
    }
    __syncthreads();
    {
        const int w  = tid & 127;
        const int nh = (tid >> 7) * 64;
        float lm = 0.f;
        float* dst = A2T + ((size_t)b * NFEAT + w) * NNODE + nbase + nh;
        #pragma unroll
        for (int g = 0; g < 16; g++) {
            float4 v;
            v.x = sm[(nh + g * 4 + 0) * 132 + w];
            v.y = sm[(nh + g * 4 + 1) * 132 + w];
            v.z = sm[(nh + g * 4 + 2) * 132 + w];
            v.w = sm[(nh + g * 4 + 3) * 132 + w];
            lm = fmaxf(lm, fmaxf(fmaxf(fabsf(v.x), fabsf(v.y)), fmaxf(fabsf(v.z), fabsf(v.w))));
            *(float4*)(dst + g * 4) = v;
        }
        #pragma unroll
        for (int o = 16; o > 0; o >>= 1) lm = fmaxf(lm, __shfl_xor_sync(0xFFFFFFFFu, lm, o));
        __shared__ float red[8];
        if ((tid & 31) == 0) red[tid >> 5] = lm;
        __syncthreads();
        if (tid == 0) {
            float bm = red[0];
            #pragma unroll
            for (int i = 1; i < 8; i++) bm = fmaxf(bm, red[i]);
            atomicMax(mx, __float_as_uint(bm));
        }
    }
}

// ---------------------------------------------------------------------------
// Launch sequence
// ---------------------------------------------------------------------------
extern "C" void kernel_launch(void* const* d_in, const int* in_sizes, int n_in,
                              void* d_out, int out_size)
{
    const float* x   = (const float*)d_in[0];
    const float* adj = (const float*)d_in[1];
    const float* W1  = (const float*)d_in[2];
    const float* b1  = (const float*)d_in[3];
    const float* W2  = (const float*)d_in[4];
    const float* b2  = (const float*)d_in[5];
    float* out = (float*)d_out;

    int8_t *pA1, *pA2, *pB1, *pB2; float *pT, *pM; unsigned* pS;
    __nv_bfloat16 *pW1h, *pW1l, *pW2h, *pW2l;
    cudaGetSymbolAddress((void**)&pA1, g_A1);
    cudaGetSymbolAddress((void**)&pA2, g_A2q);
    cudaGetSymbolAddress((void**)&pB1, g_B1);
    cudaGetSymbolAddress((void**)&pB2, g_B2q);
    cudaGetSymbolAddress((void**)&pT,  g_T);
    cudaGetSymbolAddress((void**)&pM,  g_A2T);
    cudaGetSymbolAddress((void**)&pS,  g_scal);
    cudaGetSymbolAddress((void**)&pW1h, g_W1Th);
    cudaGetSymbolAddress((void**)&pW1l, g_W1Tl);
    cudaGetSymbolAddress((void**)&pW2h, g_W2Th);
    cudaGetSymbolAddress((void**)&pW2l, g_W2Tl);

    cudaFuncSetAttribute(gemm_s8,    cudaFuncAttributeMaxDynamicSharedMemorySize, SM_TOTAL);
    cudaFuncSetAttribute(mlp_tensor, cudaFuncAttributeMaxDynamicSharedMemorySize, M_SM);

    const size_t nadj = (size_t)NNODE * NNODE;              // 16.8M
    const size_t nx   = (size_t)BATCH * NNODE * NFEAT;      // 33.5M
    const dim3 ggrid(NNODE / 128, BATCH);                   // 32 x 64
    const int  nrows = BATCH * NNODE;                       // 262144

    // scales
    zero_scal<<<1, 1>>>(pS);
    rmax4<<<2048, 256>>>((const float4*)adj, (int)(nadj / 4), pS + 0);
    rmax4<<<2048, 256>>>((const float4*)x,   (int)(nx / 4),   pS + 1);

    // quantize inputs + weight prep
    quant_pt<<<(unsigned)(nadj / (256 * 4)), 256>>>(adj, pA1, pA2, pS + 0);
    quant_xT<<<dim3(NNODE / 32, NFEAT / 32, BATCH), dim3(32, 8)>>>(x, pB1, pB2, pS + 1);
    wprep1<<<NHID * NFEAT / 256, 256>>>(W1, pW1h, pW1l);
    wprep2<<<NFEAT * NHID / 256, 256>>>(W2, pW2h, pW2l);

    // K1: T = adj @ x
    gemm_s8<<<ggrid, 512, SM_TOTAL>>>(pA1, pA2, pB1, pB2, pT, pS + 0, pS + 1,
                                      nullptr, nullptr);
    // K2: A2T = relu(T@W1+b1)@W2 (tensor-core), transposed + absmax
    mlp_tensor<<<nrows / 128, 256, M_SM>>>(pT, pW1h, pW1l, pW2h, pW2l, b1, pM, pS + 2);
    // quantize MLP output (already [b][w][n])
    quant_pt<<<(unsigned)(nx / (256 * 4)), 256>>>(pM, pB1, pB2, pS + 2);
    // K3 + fused bias/log_softmax -> out
    gemm_s8<<<ggrid, 512, SM_TOTAL>>>(pA1, pA2, pB1, pB2, nullptr, pS + 0, pS + 2,
                                      out, b2);

    (void)in_sizes; (void)n_in; (void)out_size;
}

// round 13
// speedup vs baseline: 1.3015x; 1.3015x over previous
#include <cuda_runtime.h>
#include <cuda_bf16.h>
#include <math.h>
#include <stdint.h>

// Problem dims (fixed by reference)
#define BATCH   64          // B*L
#define NNODE   4096        // H
#define NFEAT   128         // W == nclass
#define NHID    256

// ---------------------------------------------------------------------------
// Static device scratch (no allocations allowed)
// ---------------------------------------------------------------------------
__device__ int8_t g_A1 [(size_t)NNODE * NNODE];                  // adj single-level
__device__ int8_t g_B1 [(size_t)BATCH * NFEAT * NNODE];          // B level-1 [b][w][k]
__device__ int8_t g_B2q[(size_t)BATCH * NFEAT * NNODE];          // B level-2
__device__ float  g_T  [(size_t)BATCH * NNODE * NFEAT];          // GEMM1 out
__device__ float  g_A2T[(size_t)BATCH * NFEAT * NNODE];          // MLP out transposed
__device__ unsigned g_scal[3];                                   // absmax: adj, x, mlp
__device__ __nv_bfloat16 g_W1Th[NHID * NFEAT];                   // W1^T hi [256][128]
__device__ __nv_bfloat16 g_W1Tl[NHID * NFEAT];                   // W1^T lo
__device__ __nv_bfloat16 g_W2Th[NFEAT * NHID];                   // W2^T hi [128][256]
__device__ __nv_bfloat16 g_W2Tl[NFEAT * NHID];                   // W2^T lo

// ---------------------------------------------------------------------------
// PTX helpers (sm_80-era: ldmatrix / mma.sync / cp.async)
// ---------------------------------------------------------------------------
__device__ __forceinline__ uint32_t smem_u32(const void* p) {
    uint32_t a;
    asm("{ .reg .u64 t; cvta.to.shared.u64 t, %1; cvt.u32.u64 %0, t; }" : "=r"(a) : "l"(p));
    return a;
}

#define LDSM4(r, a)                                                                 \
    asm volatile("ldmatrix.sync.aligned.m8n8.x4.shared.b16 {%0,%1,%2,%3}, [%4];"    \
        : "=r"((r)[0]), "=r"((r)[1]), "=r"((r)[2]), "=r"((r)[3]) : "r"(a))

#define LDSM2(r, a)                                                                 \
    asm volatile("ldmatrix.sync.aligned.m8n8.x2.shared.b16 {%0,%1}, [%2];"          \
        : "=r"((r)[0]), "=r"((r)[1]) : "r"(a))

#define MMA_S8(c, a, bb)                                                            \
    asm volatile("mma.sync.aligned.m16n8k32.row.col.s32.s8.s8.s32 "                 \
        "{%0,%1,%2,%3}, {%4,%5,%6,%7}, {%8,%9}, {%0,%1,%2,%3};"                     \
        : "+r"((c)[0]), "+r"((c)[1]), "+r"((c)[2]), "+r"((c)[3])                    \
        : "r"((a)[0]), "r"((a)[1]), "r"((a)[2]), "r"((a)[3]),                       \
          "r"((bb)[0]), "r"((bb)[1]))

#define MMA_BF16(c, a, bb)                                                          \
    asm volatile("mma.sync.aligned.m16n8k16.row.col.f32.bf16.bf16.f32 "             \
        "{%0,%1,%2,%3}, {%4,%5,%6,%7}, {%8,%9}, {%0,%1,%2,%3};"                     \
        : "+f"((c)[0]), "+f"((c)[1]), "+f"((c)[2]), "+f"((c)[3])                    \
        : "r"((a)[0]), "r"((a)[1]), "r"((a)[2]), "r"((a)[3]),                       \
          "r"((bb)[0]), "r"((bb)[1]))

#define CP16(dst, src) asm volatile("cp.async.cg.shared.global [%0], [%1], 16;" :: "r"(dst), "l"(src) : "memory")
#define CP_COMMIT()    asm volatile("cp.async.commit_group;" ::: "memory")
#define CP_WAIT1()     asm volatile("cp.async.wait_group 1;" ::: "memory")
#define CP_WAIT0()     asm volatile("cp.async.wait_group 0;" ::: "memory")

// two-level symmetric quantization: v ~= (max/127) * (q1 + q2/256)
__device__ __forceinline__ void q2lvl(float v, float inv, int& o1, int& o2) {
    float q  = v * inv;
    float r1 = rintf(q);
    r1 = fminf(127.f, fmaxf(-127.f, r1));
    float r2 = rintf((q - r1) * 256.f);
    r2 = fminf(127.f, fmaxf(-127.f, r2));
    o1 = (int)r1; o2 = (int)r2;
}

__device__ __forceinline__ void bf16split(float v, unsigned short& h, unsigned short& l) {
    __nv_bfloat16 hb = __float2bfloat16_rn(v);
    h = __bfloat16_as_ushort(hb);
    l = __bfloat16_as_ushort(__float2bfloat16_rn(v - __bfloat162float(hb)));
}

// ---------------------------------------------------------------------------
// tiny kernels
// ---------------------------------------------------------------------------
__global__ void zero_scal(unsigned* s) { s[0] = 0u; s[1] = 0u; s[2] = 0u; }

__global__ void __launch_bounds__(256)
rmax4(const float4* __restrict__ p, int n4, unsigned* out)
{
    float m = 0.f;
    for (int i = blockIdx.x * blockDim.x + threadIdx.x; i < n4; i += gridDim.x * blockDim.x) {
        float4 v = p[i];
        m = fmaxf(m, fmaxf(fmaxf(fabsf(v.x), fabsf(v.y)), fmaxf(fabsf(v.z), fabsf(v.w))));
    }
    #pragma unroll
    for (int o = 16; o > 0; o >>= 1) m = fmaxf(m, __shfl_xor_sync(0xFFFFFFFFu, m, o));
    __shared__ float red[8];
    if ((threadIdx.x & 31) == 0) red[threadIdx.x >> 5] = m;
    __syncthreads();
    if (threadIdx.x == 0) {
        float b = red[0];
        #pragma unroll
        for (int i = 1; i < 8; i++) b = fmaxf(b, red[i]);
        atomicMax(out, __float_as_uint(b));
    }
}

// weight transpose + bf16 split preps
__global__ void __launch_bounds__(256)
wprep1(const float* __restrict__ W1, __nv_bfloat16* __restrict__ h, __nv_bfloat16* __restrict__ l)
{
    int gid = blockIdx.x * 256 + threadIdx.x;           // 32768
    int r = gid >> 7, c = gid & 127;                    // out [256][128]
    unsigned short hh, ll;
    bf16split(W1[(size_t)c * NHID + r], hh, ll);
    h[gid] = __ushort_as_bfloat16(hh);
    l[gid] = __ushort_as_bfloat16(ll);
}
__global__ void __launch_bounds__(256)
wprep2(const float* __restrict__ W2, __nv_bfloat16* __restrict__ h, __nv_bfloat16* __restrict__ l)
{
    int gid = blockIdx.x * 256 + threadIdx.x;           // 32768
    int r = gid >> 8, c = gid & 255;                    // out [128][256]
    unsigned short hh, ll;
    bf16split(W2[(size_t)c * NFEAT + r], hh, ll);
    h[gid] = __ushort_as_bfloat16(hh);
    l[gid] = __ushort_as_bfloat16(ll);
}

// ---------------------------------------------------------------------------
// single-level quantize (adj)
// ---------------------------------------------------------------------------
__global__ void __launch_bounds__(256)
quant1_pt(const float* __restrict__ src, int8_t* __restrict__ d1,
          const unsigned* __restrict__ mx)
{
    const float inv = 127.f / fmaxf(__uint_as_float(*mx), 1e-30f);
    const size_t i = ((size_t)blockIdx.x * 256 + threadIdx.x) * 4;
    float4 v = *(const float4*)(src + i);
    float q0 = fminf(127.f, fmaxf(-127.f, rintf(v.x * inv)));
    float q1 = fminf(127.f, fmaxf(-127.f, rintf(v.y * inv)));
    float q2 = fminf(127.f, fmaxf(-127.f, rintf(v.z * inv)));
    float q3 = fminf(127.f, fmaxf(-127.f, rintf(v.w * inv)));
    *(char4*)(d1 + i) = make_char4((char)(int)q0, (char)(int)q1,
                                   (char)(int)q2, (char)(int)q3);
}

// ---------------------------------------------------------------------------
// pointwise 2-level quantize (MLP output, already [b][w][n])
// ---------------------------------------------------------------------------
__global__ void __launch_bounds__(256)
quant_pt(const float* __restrict__ src, int8_t* __restrict__ d1,
         int8_t* __restrict__ d2, const unsigned* __restrict__ mx)
{
    const float inv = 127.f / fmaxf(__uint_as_float(*mx), 1e-30f);
    const size_t i = ((size_t)blockIdx.x * 256 + threadIdx.x) * 4;
    float4 v = *(const float4*)(src + i);
    int a1, a2, b1, b2, c1, c2, e1, e2;
    q2lvl(v.x, inv, a1, a2); q2lvl(v.y, inv, b1, b2);
    q2lvl(v.z, inv, c1, c2); q2lvl(v.w, inv, e1, e2);
    *(char4*)(d1 + i) = make_char4((char)a1, (char)b1, (char)c1, (char)e1);
    *(char4*)(d2 + i) = make_char4((char)a2, (char)b2, (char)c2, (char)e2);
}

// ---------------------------------------------------------------------------
// x [b][n][w] fp32 -> int8x2 transposed [b][w][n]
// ---------------------------------------------------------------------------
__global__ void __launch_bounds__(256)
quant_xT(const float* __restrict__ x, int8_t* __restrict__ d1,
         int8_t* __restrict__ d2, const unsigned* __restrict__ mx)
{
    __shared__ float t[32][33];
    const float inv = 127.f / fmaxf(__uint_as_float(*mx), 1e-30f);
    const int tx = threadIdx.x, ty = threadIdx.y;       // 32 x 8
    const int n0 = blockIdx.x * 32, w0 = blockIdx.y * 32, b = blockIdx.z;
    #pragma unroll
    for (int j = 0; j < 4; j++) {
        int n = n0 + ty + j * 8;
        t[ty + j * 8][tx] = x[((size_t)b * NNODE + n) * NFEAT + w0 + tx];
    }
    __syncthreads();
    #pragma unroll
    for (int j = 0; j < 4; j++) {
        int w = w0 + ty + j * 8;
        int q1, q2;
        q2lvl(t[tx][ty + j * 8], inv, q1, q2);
        size_t o = ((size_t)b * NFEAT + w) * NNODE + n0 + tx;
        d1[o] = (int8_t)q1; d2[o] = (int8_t)q2;
    }
}

// ---------------------------------------------------------------------------
// int8 GEMM (A single-level, B two-level): C = sum_k a1[n,k]*(b1+b2/256)[w,k]
// 2 MMAs per k32 (was 3). 256 thr, warp tile 64x32 (R11 layout).
// If out2 != null: fused epilogue out2 = log_softmax(C + bias2) (GEMM2 mode).
// ---------------------------------------------------------------------------
#define KC       128
#define NSTAGE   (NNODE / KC)              // 32
#define ROW_B    144
#define TILE_B   (128 * ROW_B)             // 18432
#define STAGE_B  (3 * TILE_B)              // 55296  (A1, B1, B2)
#define SM_TOTAL (2 * STAGE_B)             // 110592

__global__ void __launch_bounds__(256, 1)
gemm_s8(const int8_t* __restrict__ A1,
        const int8_t* __restrict__ B1, const int8_t* __restrict__ B2q,
        float* __restrict__ C,
        const unsigned* __restrict__ maxA, const unsigned* __restrict__ maxB,
        float* __restrict__ out2, const float* __restrict__ bias2)
{
    extern __shared__ __align__(16) char smem[];
    const uint32_t sb = smem_u32(smem);
    const int tid  = threadIdx.x;
    const int wid  = tid >> 5, lane = tid & 31;
    const int wm   = wid & 1;
    const int wn   = wid >> 1;
    const int n0 = blockIdx.x * 128, b = blockIdx.y;

    const int8_t* tb[3] = {
        A1  + (size_t)n0 * NNODE,
        B1  + (size_t)b * NFEAT * NNODE, B2q + (size_t)b * NFEAT * NNODE };

    // cp.async plan: 3 tiles x 1024 chunks(16B) = 3072 / 256 thr = 12 each.
    const int c16   = (tid & 7) * 16;
    const int rbase = tid >> 3;            // 0..31

    const uint32_t offA = (uint32_t)(wm * 64 + (lane & 15)) * ROW_B + (lane >> 4) * 16;
    const uint32_t offB = (uint32_t)(wn * 32 + (lane & 7)) * ROW_B + ((lane >> 3) & 1) * 16;

    int p1[4][4][4], p2[4][4][4];
    #pragma unroll
    for (int mi = 0; mi < 4; mi++)
        #pragma unroll
        for (int ni = 0; ni < 4; ni++)
            #pragma unroll
            for (int e = 0; e < 4; e++) { p1[mi][ni][e] = 0; p2[mi][ni][e] = 0; }

    #pragma unroll
    for (int j = 0; j < 12; j++) {
        const int row = (j & 3) * 32 + rbase;
        CP16(sb + (j >> 2) * TILE_B + row * ROW_B + c16,
             tb[j >> 2] + (size_t)row * NNODE + c16);
    }
    CP_COMMIT();

    for (int i = 0; i < NSTAGE; i++) {
        const int buf = i & 1;
        if (i < NSTAGE - 1) {
            const uint32_t dbase = sb + (buf ^ 1) * STAGE_B;
            const int koff = (i + 1) * KC;
            #pragma unroll
            for (int j = 0; j < 12; j++) {
                const int row = (j & 3) * 32 + rbase;
                CP16(dbase + (j >> 2) * TILE_B + row * ROW_B + c16,
                     tb[j >> 2] + (size_t)row * NNODE + koff + c16);
            }
            CP_COMMIT();
            CP_WAIT1();
        } else {
            CP_WAIT0();
        }
        __syncthreads();

        const uint32_t s = sb + buf * STAGE_B;
        #pragma unroll
        for (int ks = 0; ks < 4; ks++) {
            uint32_t a1f[4][4];
            #pragma unroll
            for (int mi = 0; mi < 4; mi++) {
                const uint32_t a = s + offA + mi * (16 * ROW_B) + ks * 32;
                LDSM4(a1f[mi], a);
            }
            #pragma unroll
            for (int ni = 0; ni < 4; ni++) {
                uint32_t b1f[2], b2f[2];
                const uint32_t a = s + TILE_B + offB + ni * (8 * ROW_B) + ks * 32;
                LDSM2(b1f, a);
                LDSM2(b2f, a + TILE_B);
                #pragma unroll
                for (int mi = 0; mi < 4; mi++) {
                    MMA_S8(p1[mi][ni], a1f[mi], b1f);
                    MMA_S8(p2[mi][ni], a1f[mi], b2f);
                }
            }
        }
        __syncthreads();
    }

    const float mA = __uint_as_float(*maxA), mB = __uint_as_float(*maxB);
    const float s1 = (mA * mB) * (1.f / 16129.f);   // /127^2
    const float s2 = s1 * (1.f / 256.f);
    const int mrow = wm * 64 + (lane >> 2);
    const int ncol = wn * 32 + (lane & 3) * 2;

    if (out2 == nullptr) {
        float* Cb = C + ((size_t)b * NNODE + n0) * NFEAT;
        #pragma unroll
        for (int mi = 0; mi < 4; mi++) {
            #pragma unroll
            for (int ni = 0; ni < 4; ni++) {
                float* q0 = Cb + (size_t)(mrow + mi * 16) * NFEAT + ncol + ni * 8;
                float* q1 = q0 + 8 * NFEAT;
                *(float2*)q0 = make_float2(s1 * (float)p1[mi][ni][0] + s2 * (float)p2[mi][ni][0],
                                           s1 * (float)p1[mi][ni][1] + s2 * (float)p2[mi][ni][1]);
                *(float2*)q1 = make_float2(s1 * (float)p1[mi][ni][2] + s2 * (float)p2[mi][ni][2],
                                           s1 * (float)p1[mi][ni][3] + s2 * (float)p2[mi][ni][3]);
            }
        }
    } else {
        // fused bias + log_softmax epilogue: bounce acc through smem (stages dead)
        float* sm = (float*)smem;                       // [128][132] fp32
        #pragma unroll
        for (int mi = 0; mi < 4; mi++) {
            #pragma unroll
            for (int ni = 0; ni < 4; ni++) {
                const int r0 = mrow + mi * 16, c0 = ncol + ni * 8;
                sm[r0 * 132 + c0]           = s1 * (float)p1[mi][ni][0] + s2 * (float)p2[mi][ni][0];
                sm[r0 * 132 + c0 + 1]       = s1 * (float)p1[mi][ni][1] + s2 * (float)p2[mi][ni][1];
                sm[(r0 + 8) * 132 + c0]     = s1 * (float)p1[mi][ni][2] + s2 * (float)p2[mi][ni][2];
                sm[(r0 + 8) * 132 + c0 + 1] = s1 * (float)p1[mi][ni][3] + s2 * (float)p2[mi][ni][3];
            }
        }
        __syncthreads();
        const float4 bb = ((const float4*)bias2)[lane];
        for (int rr = wid * 16; rr < wid * 16 + 16; rr++) {
            float4 v = *(float4*)&sm[rr * 132 + lane * 4];
            float v0 = v.x + bb.x, v1 = v.y + bb.y, v2 = v.z + bb.z, v3 = v.w + bb.w;
            float m = fmaxf(fmaxf(v0, v1), fmaxf(v2, v3));
            #pragma unroll
            for (int o = 16; o > 0; o >>= 1) m = fmaxf(m, __shfl_xor_sync(0xFFFFFFFFu, m, o));
            float ss = expf(v0 - m) + expf(v1 - m) + expf(v2 - m) + expf(v3 - m);
            #pragma unroll
            for (int o = 16; o > 0; o >>= 1) ss += __shfl_xor_sync(0xFFFFFFFFu, ss, o);
            const float lse = m + logf(ss);
            float4 o4; o4.x = v0 - lse; o4.y = v1 - lse; o4.z = v2 - lse; o4.w = v3 - lse;
            *(float4*)(out2 + ((size_t)b * NNODE + n0 + rr) * NFEAT + lane * 4) = o4;
        }
    }
}

// ---------------------------------------------------------------------------
// MLP on tensor cores (bf16 3-term split both layers) — unchanged from R11.
// Per CTA: 128 rows. A2T[b][w][n] = relu(T @ W1 + b1) @ W2, + global absmax.
// ---------------------------------------------------------------------------
#define MROWB 272                                      // 256B data + 16 pad
#define MLVL  (128 * MROWB)                            // 34816
#define M_RA  0
#define M_RB  (2 * MLVL)                               // 69632
#define M_RC  (4 * MLVL)                               // 139264
#define M_SM  (6 * MLVL)                               // 208896

__global__ void __launch_bounds__(256, 1)
mlp_tensor(const float* __restrict__ T,
           const __nv_bfloat16* __restrict__ W1Th, const __nv_bfloat16* __restrict__ W1Tl,
           const __nv_bfloat16* __restrict__ W2Th, const __nv_bfloat16* __restrict__ W2Tl,
           const float* __restrict__ b1,
           float* __restrict__ A2T, unsigned* __restrict__ mx)
{
    extern __shared__ __align__(16) char smem[];
    const uint32_t sb = smem_u32(smem);
    const int tid  = threadIdx.x;
    const int wid  = tid >> 5, lane = tid & 31;
    const int wm   = wid & 1, wn = wid >> 1;
    const size_t row0 = (size_t)blockIdx.x * 128;
    const int b     = (int)(row0 >> 12);
    const int nbase = (int)(row0 & 4095);

    // --- issue W1T half0 loads, then convert T while they fly ---
    {
        #pragma unroll
        for (int j = 0; j < 8; j++) {
            int cid = j * 256 + tid;         // 2048
            int r = cid >> 4, c = cid & 15;
            CP16(sb + M_RB + r * MROWB + c * 16,        W1Th + (size_t)r * NFEAT + c * 8);
            CP16(sb + M_RB + MLVL + r * MROWB + c * 16, W1Tl + (size_t)r * NFEAT + c * 8);
        }
        CP_COMMIT();
    }
    {
        const int r  = tid >> 1;
        const int wb = (tid & 1) * 64;
        const float* src = T + (row0 + r) * NFEAT + wb;
        #pragma unroll
        for (int i = 0; i < 16; i++) {
            float4 v = *(const float4*)(src + i * 4);
            unsigned short h0,l0,h1,l1,h2,l2,h3,l3;
            bf16split(v.x, h0, l0); bf16split(v.y, h1, l1);
            bf16split(v.z, h2, l2); bf16split(v.w, h3, l3);
            uint32_t hi01 = (uint32_t)h0 | ((uint32_t)h1 << 16);
            uint32_t hi23 = (uint32_t)h2 | ((uint32_t)h3 << 16);
            uint32_t lo01 = (uint32_t)l0 | ((uint32_t)l1 << 16);
            uint32_t lo23 = (uint32_t)l2 | ((uint32_t)l3 << 16);
            const uint32_t base = sb + M_RA + r * MROWB + (wb + i * 4) * 2;
            asm volatile("st.shared.u32 [%0], %1;" :: "r"(base),     "r"(hi01));
            asm volatile("st.shared.u32 [%0], %1;" :: "r"(base + 4), "r"(hi23));
            asm volatile("st.shared.u32 [%0], %1;" :: "r"(base + MLVL),     "r"(lo01));
            asm volatile("st.shared.u32 [%0], %1;" :: "r"(base + MLVL + 4), "r"(lo23));
        }
    }
    CP_WAIT0();
    __syncthreads();

    const uint32_t offA = (uint32_t)(wm * 64 + (lane & 15)) * MROWB + (lane >> 4) * 16;
    const uint32_t offB = (uint32_t)(wn * 32 + (lane & 7)) * MROWB + ((lane >> 3) & 1) * 16;

    float acc2[4][4][4];
    #pragma unroll
    for (int mi = 0; mi < 4; mi++)
        #pragma unroll
        for (int ni = 0; ni < 4; ni++)
            #pragma unroll
            for (int e = 0; e < 4; e++) acc2[mi][ni][e] = 0.f;

    #pragma unroll 1
    for (int half = 0; half < 2; half++) {
        // ---- layer 1 half: h[:, half*128 .. half*128+127] = T @ W1T-half ----
        float acc1[4][4][4];
        #pragma unroll
        for (int mi = 0; mi < 4; mi++)
            #pragma unroll
            for (int ni = 0; ni < 4; ni++)
                #pragma unroll
                for (int e = 0; e < 4; e++) acc1[mi][ni][e] = 0.f;

        #pragma unroll
        for (int ks = 0; ks < 8; ks++) {
            uint32_t ah[4][4], al[4][4];
            #pragma unroll
            for (int mi = 0; mi < 4; mi++) {
                const uint32_t a = sb + M_RA + offA + mi * (16 * MROWB) + ks * 32;
                LDSM4(ah[mi], a);
                LDSM4(al[mi], a + MLVL);
            }
            #pragma unroll
            for (int ni = 0; ni < 4; ni++) {
                uint32_t bh[2], bl[2];
                const uint32_t a = sb + M_RB + offB + ni * (8 * MROWB) + ks * 32;
                LDSM2(bh, a);
                LDSM2(bl, a + MLVL);
                #pragma unroll
                for (int mi = 0; mi < 4; mi++) {
                    MMA_BF16(acc1[mi][ni], ah[mi], bh);
                    MMA_BF16(acc1[mi][ni], ah[mi], bl);
                    MMA_BF16(acc1[mi][ni], al[mi], bh);
                }
            }
        }
        __syncthreads();                     // everyone done reading RB

        // load W2T half into RB
        #pragma unroll
        for (int j = 0; j < 8; j++) {
            int cid = j * 256 + tid;
            int r = cid >> 4, c = cid & 15;
            CP16(sb + M_RB + r * MROWB + c * 16,
                 W2Th + (size_t)r * NHID + half * 128 + c * 8);
            CP16(sb + M_RB + MLVL + r * MROWB + c * 16,
                 W2Tl + (size_t)r * NHID + half * 128 + c * 8);
        }
        CP_COMMIT();

        // relu + bias + bf16 split h -> RC (overlaps with W2T copy)
        {
            const int cb = wn * 32 + (lane & 3) * 2;
            #pragma unroll
            for (int ni = 0; ni < 4; ni++) {
                const float2 bv = *(const float2*)(b1 + half * 128 + cb + ni * 8);
                #pragma unroll
                for (int mi = 0; mi < 4; mi++) {
                    const int r = wm * 64 + (lane >> 2) + mi * 16;
                    float h0 = fmaxf(acc1[mi][ni][0] + bv.x, 0.f);
                    float h1 = fmaxf(acc1[mi][ni][1] + bv.y, 0.f);
                    float h2 = fmaxf(acc1[mi][ni][2] + bv.x, 0.f);
                    float h3 = fmaxf(acc1[mi][ni][3] + bv.y, 0.f);
                    unsigned short a0,a1,a2,a3,b0,bb1,b2q,b3;
                    bf16split(h0, a0, b0); bf16split(h1, a1, bb1);
                    bf16split(h2, a2, b2q); bf16split(h3, a3, b3);
                    const uint32_t c2 = (cb + ni * 8) * 2;
                    uint32_t ad0 = sb + M_RC + r * MROWB + c2;
                    uint32_t ad1 = sb + M_RC + (r + 8) * MROWB + c2;
                    uint32_t hi0 = (uint32_t)a0 | ((uint32_t)a1 << 16);
                    uint32_t hi1 = (uint32_t)a2 | ((uint32_t)a3 << 16);
                    uint32_t lo0 = (uint32_t)b0 | ((uint32_t)bb1 << 16);
                    uint32_t lo1 = (uint32_t)b2q | ((uint32_t)b3 << 16);
                    asm volatile("st.shared.u32 [%0], %1;" :: "r"(ad0), "r"(hi0));
                    asm volatile("st.shared.u32 [%0], %1;" :: "r"(ad1), "r"(hi1));
                    asm volatile("st.shared.u32 [%0], %1;" :: "r"(ad0 + MLVL), "r"(lo0));
                    asm volatile("st.shared.u32 [%0], %1;" :: "r"(ad1 + MLVL), "r"(lo1));
                }
            }
        }
        CP_WAIT0();
        __syncthreads();                     // h + W2T half ready

        // ---- layer 2 half: acc2 += h_half @ W2T-half ----
        #pragma unroll
        for (int ks = 0; ks < 8; ks++) {
            uint32_t ah[4][4], al[4][4];
            #pragma unroll
            for (int mi = 0; mi < 4; mi++) {
                const uint32_t a = sb + M_RC + offA + mi * (16 * MROWB) + ks * 32;
                LDSM4(ah[mi], a);
                LDSM4(al[mi], a + MLVL);
            }
            #pragma unroll
            for (int ni = 0; ni < 4; ni++) {
                uint32_t bh[2], bl[2];
                const uint32_t a = sb + M_RB + offB + ni * (8 * MROWB) + ks * 32;
                LDSM2(bh, a);
                LDSM2(bl, a + MLVL);
                #pragma unroll
                for (int mi = 0; mi < 4; mi++) {
                    MMA_BF16(acc2[mi][ni], ah[mi], bh);
                    MMA_BF16(acc2[mi][ni], ah[mi], bl);
                    MMA_BF16(acc2[mi][ni], al[mi], bh);
                }
            }
        }
        if (half == 0) {
            __syncthreads();                 // done reading RB; reload W1T half1
            #pragma unroll
            for (int j = 0; j < 8; j++) {
                int cid = j * 256 + tid;
                int r = cid >> 4, c = cid & 15;
                CP16(sb + M_RB + r * MROWB + c * 16,
                     W1Th + (size_t)(128 + r) * NFEAT + c * 8);
                CP16(sb + M_RB + MLVL + r * MROWB + c * 16,
                     W1Tl + (size_t)(128 + r) * NFEAT + c * 8);
            }
            CP_COMMIT();
            CP_WAIT0();
            __syncthreads();
        }
    }

    // ---- epilogue: transpose via smem (RA/RB dead), write A2T + absmax ----
    __syncthreads();
    float* sm = (float*)smem;                // [128][132] fp32 in RA+RB space
    {
        const int mrow = wm * 64 + (lane >> 2);
        const int ncol = wn * 32 + (lane & 3) * 2;
        #pragma unroll
        for (int mi = 0; mi < 4; mi++)
            #pragma unroll
            for (int ni = 0; ni < 4; ni++) {
                const int r0 = mrow + mi * 16, c0 = ncol + ni * 8;
                sm[r0 * 132 + c0]           = acc2[mi][ni][0];
                sm[r0 * 132 + c0 + 1]       = acc2[mi][ni][1];
                sm[(r0 + 8) * 132 + c0]     = acc2[mi][ni][2];
                sm[(r0 + 8) * 132 + c0 + 1] = acc2[mi][ni][3];
            }
    }
    __syncthreads();
    {
        const int w  = tid & 127;
        const int nh = (tid >> 7) * 64;
        float lm = 0.f;
        float* dst = A2T + ((size_t)b * NFEAT + w) * NNODE + nbase + nh;
        #pragma unroll
        for (int g = 0; g < 16; g++) {
            float4 v;
            v.x = sm[(nh + g * 4 + 0) * 132 + w];
            v.y = sm[(nh + g * 4 + 1) * 132 + w];
            v.z = sm[(nh + g * 4 + 2) * 132 + w];
            v.w = sm[(nh + g * 4 + 3) * 132 + w];
            lm = fmaxf(lm, fmaxf(fmaxf(fabsf(v.x), fabsf(v.y)), fmaxf(fabsf(v.z), fabsf(v.w))));
            *(float4*)(dst + g * 4) = v;
        }
        #pragma unroll
        for (int o = 16; o > 0; o >>= 1) lm = fmaxf(lm, __shfl_xor_sync(0xFFFFFFFFu, lm, o));
        __shared__ float red[8];
        if ((tid & 31) == 0) red[tid >> 5] = lm;
        __syncthreads();
        if (tid == 0) {
            float bm = red[0];
            #pragma unroll
            for (int i = 1; i < 8; i++) bm = fmaxf(bm, red[i]);
            atomicMax(mx, __float_as_uint(bm));
        }
    }
}

// ---------------------------------------------------------------------------
// Launch sequence
// ---------------------------------------------------------------------------
extern "C" void kernel_launch(void* const* d_in, const int* in_sizes, int n_in,
                              void* d_out, int out_size)
{
    const float* x   = (const float*)d_in[0];
    const float* adj = (const float*)d_in[1];
    const float* W1  = (const float*)d_in[2];
    const float* b1  = (const float*)d_in[3];
    const float* W2  = (const float*)d_in[4];
    const float* b2  = (const float*)d_in[5];
    float* out = (float*)d_out;

    int8_t *pA1, *pB1, *pB2; float *pT, *pM; unsigned* pS;
    __nv_bfloat16 *pW1h, *pW1l, *pW2h, *pW2l;
    cudaGetSymbolAddress((void**)&pA1, g_A1);
    cudaGetSymbolAddress((void**)&pB1, g_B1);
    cudaGetSymbolAddress((void**)&pB2, g_B2q);
    cudaGetSymbolAddress((void**)&pT,  g_T);
    cudaGetSymbolAddress((void**)&pM,  g_A2T);
    cudaGetSymbolAddress((void**)&pS,  g_scal);
    cudaGetSymbolAddress((void**)&pW1h, g_W1Th);
    cudaGetSymbolAddress((void**)&pW1l, g_W1Tl);
    cudaGetSymbolAddress((void**)&pW2h, g_W2Th);
    cudaGetSymbolAddress((void**)&pW2l, g_W2Tl);

    cudaFuncSetAttribute(gemm_s8,    cudaFuncAttributeMaxDynamicSharedMemorySize, SM_TOTAL);
    cudaFuncSetAttribute(mlp_tensor, cudaFuncAttributeMaxDynamicSharedMemorySize, M_SM);

    const size_t nadj = (size_t)NNODE * NNODE;              // 16.8M
    const size_t nx   = (size_t)BATCH * NNODE * NFEAT;      // 33.5M
    const dim3 ggrid(NNODE / 128, BATCH);                   // 32 x 64
    const int  nrows = BATCH * NNODE;                       // 262144

    // scales
    zero_scal<<<1, 1>>>(pS);
    rmax4<<<2048, 256>>>((const float4*)adj, (int)(nadj / 4), pS + 0);
    rmax4<<<2048, 256>>>((const float4*)x,   (int)(nx / 4),   pS + 1);

    // quantize inputs + weight prep
    quant1_pt<<<(unsigned)(nadj / (256 * 4)), 256>>>(adj, pA1, pS + 0);
    quant_xT<<<dim3(NNODE / 32, NFEAT / 32, BATCH), dim3(32, 8)>>>(x, pB1, pB2, pS + 1);
    wprep1<<<NHID * NFEAT / 256, 256>>>(W1, pW1h, pW1l);
    wprep2<<<NFEAT * NHID / 256, 256>>>(W2, pW2h, pW2l);

    // K1: T = adj @ x
    gemm_s8<<<ggrid, 256, SM_TOTAL>>>(pA1, pB1, pB2, pT, pS + 0, pS + 1,
                                      nullptr, nullptr);
    // K2: A2T = relu(T@W1+b1)@W2 (tensor-core), transposed + absmax
    mlp_tensor<<<nrows / 128, 256, M_SM>>>(pT, pW1h, pW1l, pW2h, pW2l, b1, pM, pS + 2);
    // quantize MLP output (already [b][w][n])
    quant_pt<<<(unsigned)(nx / (256 * 4)), 256>>>(pM, pB1, pB2, pS + 2);
    // K3 + fused bias/log_softmax -> out
    gemm_s8<<<ggrid, 256, SM_TOTAL>>>(pA1, pB1, pB2, nullptr, pS + 0, pS + 2,
                                      out, b2);

    (void)in_sizes; (void)n_in; (void)out_size;
}

// round 14
// speedup vs baseline: 2.1138x; 1.6241x over previous
#include <cuda_runtime.h>
#include <cuda_bf16.h>
#include <math.h>
#include <stdint.h>

// Problem dims (fixed by reference)
#define BATCH   64          // B*L
#define NNODE   4096        // H
#define NFEAT   128         // W == nclass
#define NHID    256

// ---------------------------------------------------------------------------
// Static device scratch (no allocations allowed)
// ---------------------------------------------------------------------------
__device__ int8_t g_A1 [(size_t)NNODE * NNODE];                  // adj int8
__device__ int8_t g_B1 [(size_t)BATCH * NFEAT * NNODE];          // B int8 [b][w][k]
__device__ float  g_T  [(size_t)BATCH * NNODE * NFEAT];          // GEMM1 out
__device__ float  g_A2T[(size_t)BATCH * NFEAT * NNODE];          // MLP out transposed
__device__ unsigned g_scal[3];                                   // absmax: adj, x, mlp
__device__ __nv_bfloat16 g_W1Th[NHID * NFEAT];                   // W1^T hi [256][128]
__device__ __nv_bfloat16 g_W1Tl[NHID * NFEAT];                   // W1^T lo
__device__ __nv_bfloat16 g_W2Th[NFEAT * NHID];                   // W2^T hi [128][256]
__device__ __nv_bfloat16 g_W2Tl[NFEAT * NHID];                   // W2^T lo

// ---------------------------------------------------------------------------
// PTX helpers (sm_80-era: ldmatrix / mma.sync / cp.async)
// ---------------------------------------------------------------------------
__device__ __forceinline__ uint32_t smem_u32(const void* p) {
    uint32_t a;
    asm("{ .reg .u64 t; cvta.to.shared.u64 t, %1; cvt.u32.u64 %0, t; }" : "=r"(a) : "l"(p));
    return a;
}

#define LDSM4(r, a)                                                                 \
    asm volatile("ldmatrix.sync.aligned.m8n8.x4.shared.b16 {%0,%1,%2,%3}, [%4];"    \
        : "=r"((r)[0]), "=r"((r)[1]), "=r"((r)[2]), "=r"((r)[3]) : "r"(a))

#define LDSM2(r, a)                                                                 \
    asm volatile("ldmatrix.sync.aligned.m8n8.x2.shared.b16 {%0,%1}, [%2];"          \
        : "=r"((r)[0]), "=r"((r)[1]) : "r"(a))

#define MMA_S8(c, a, bb)                                                            \
    asm volatile("mma.sync.aligned.m16n8k32.row.col.s32.s8.s8.s32 "                 \
        "{%0,%1,%2,%3}, {%4,%5,%6,%7}, {%8,%9}, {%0,%1,%2,%3};"                     \
        : "+r"((c)[0]), "+r"((c)[1]), "+r"((c)[2]), "+r"((c)[3])                    \
        : "r"((a)[0]), "r"((a)[1]), "r"((a)[2]), "r"((a)[3]),                       \
          "r"((bb)[0]), "r"((bb)[1]))

#define MMA_BF16(c, a, bb)                                                          \
    asm volatile("mma.sync.aligned.m16n8k16.row.col.f32.bf16.bf16.f32 "             \
        "{%0,%1,%2,%3}, {%4,%5,%6,%7}, {%8,%9}, {%0,%1,%2,%3};"                     \
        : "+f"((c)[0]), "+f"((c)[1]), "+f"((c)[2]), "+f"((c)[3])                    \
        : "r"((a)[0]), "r"((a)[1]), "r"((a)[2]), "r"((a)[3]),                       \
          "r"((bb)[0]), "r"((bb)[1]))

#define CP16(dst, src) asm volatile("cp.async.cg.shared.global [%0], [%1], 16;" :: "r"(dst), "l"(src) : "memory")
#define CP_COMMIT()    asm volatile("cp.async.commit_group;" ::: "memory")
#define CP_WAIT1()     asm volatile("cp.async.wait_group 1;" ::: "memory")
#define CP_WAIT0()     asm volatile("cp.async.wait_group 0;" ::: "memory")

__device__ __forceinline__ void bf16split(float v, unsigned short& h, unsigned short& l) {
    __nv_bfloat16 hb = __float2bfloat16_rn(v);
    h = __bfloat16_as_ushort(hb);
    l = __bfloat16_as_ushort(__float2bfloat16_rn(v - __bfloat162float(hb)));
}

__device__ __forceinline__ int q1(float v, float inv) {
    return (int)fminf(127.f, fmaxf(-127.f, rintf(v * inv)));
}

// ---------------------------------------------------------------------------
// tiny kernels
// ---------------------------------------------------------------------------
__global__ void zero_scal(unsigned* s) { s[0] = 0u; s[1] = 0u; s[2] = 0u; }

__global__ void __launch_bounds__(256)
rmax4(const float4* __restrict__ p, int n4, unsigned* out)
{
    float m = 0.f;
    for (int i = blockIdx.x * blockDim.x + threadIdx.x; i < n4; i += gridDim.x * blockDim.x) {
        float4 v = p[i];
        m = fmaxf(m, fmaxf(fmaxf(fabsf(v.x), fabsf(v.y)), fmaxf(fabsf(v.z), fabsf(v.w))));
    }
    #pragma unroll
    for (int o = 16; o > 0; o >>= 1) m = fmaxf(m, __shfl_xor_sync(0xFFFFFFFFu, m, o));
    __shared__ float red[8];
    if ((threadIdx.x & 31) == 0) red[threadIdx.x >> 5] = m;
    __syncthreads();
    if (threadIdx.x == 0) {
        float b = red[0];
        #pragma unroll
        for (int i = 1; i < 8; i++) b = fmaxf(b, red[i]);
        atomicMax(out, __float_as_uint(b));
    }
}

// weight transpose + bf16 split preps
__global__ void __launch_bounds__(256)
wprep1(const float* __restrict__ W1, __nv_bfloat16* __restrict__ h, __nv_bfloat16* __restrict__ l)
{
    int gid = blockIdx.x * 256 + threadIdx.x;           // 32768
    int r = gid >> 7, c = gid & 127;                    // out [256][128]
    unsigned short hh, ll;
    bf16split(W1[(size_t)c * NHID + r], hh, ll);
    h[gid] = __ushort_as_bfloat16(hh);
    l[gid] = __ushort_as_bfloat16(ll);
}
__global__ void __launch_bounds__(256)
wprep2(const float* __restrict__ W2, __nv_bfloat16* __restrict__ h, __nv_bfloat16* __restrict__ l)
{
    int gid = blockIdx.x * 256 + threadIdx.x;           // 32768
    int r = gid >> 8, c = gid & 255;                    // out [128][256]
    unsigned short hh, ll;
    bf16split(W2[(size_t)c * NFEAT + r], hh, ll);
    h[gid] = __ushort_as_bfloat16(hh);
    l[gid] = __ushort_as_bfloat16(ll);
}

// ---------------------------------------------------------------------------
// single-level quantize (adj, and MLP output which is already [b][w][n])
// ---------------------------------------------------------------------------
__global__ void __launch_bounds__(256)
quant1_pt(const float* __restrict__ src, int8_t* __restrict__ d1,
          const unsigned* __restrict__ mx)
{
    const float inv = 127.f / fmaxf(__uint_as_float(*mx), 1e-30f);
    const size_t i = ((size_t)blockIdx.x * 256 + threadIdx.x) * 4;
    float4 v = *(const float4*)(src + i);
    *(char4*)(d1 + i) = make_char4((char)q1(v.x, inv), (char)q1(v.y, inv),
                                   (char)q1(v.z, inv), (char)q1(v.w, inv));
}

// ---------------------------------------------------------------------------
// x [b][n][w] fp32 -> int8 transposed [b][w][n]
// ---------------------------------------------------------------------------
__global__ void __launch_bounds__(256)
quant_xT(const float* __restrict__ x, int8_t* __restrict__ d1,
         const unsigned* __restrict__ mx)
{
    __shared__ float t[32][33];
    const float inv = 127.f / fmaxf(__uint_as_float(*mx), 1e-30f);
    const int tx = threadIdx.x, ty = threadIdx.y;       // 32 x 8
    const int n0 = blockIdx.x * 32, w0 = blockIdx.y * 32, b = blockIdx.z;
    #pragma unroll
    for (int j = 0; j < 4; j++) {
        int n = n0 + ty + j * 8;
        t[ty + j * 8][tx] = x[((size_t)b * NNODE + n) * NFEAT + w0 + tx];
    }
    __syncthreads();
    #pragma unroll
    for (int j = 0; j < 4; j++) {
        int w = w0 + ty + j * 8;
        size_t o = ((size_t)b * NFEAT + w) * NNODE + n0 + tx;
        d1[o] = (int8_t)q1(t[tx][ty + j * 8], inv);
    }
}

// ---------------------------------------------------------------------------
// int8 single-level GEMM: C[b][n][w] = s1 * sum_k a1[n,k]*b1[w,k]
// 1 MMA per k32 fragment pair. 256 thr, warp tile 64x32, 2 CTAs/SM.
// If out2 != null: fused epilogue out2 = log_softmax(C + bias2) (GEMM2 mode).
// ---------------------------------------------------------------------------
#define KC       128
#define NSTAGE   (NNODE / KC)              // 32
#define ROW_B    144
#define TILE_B   (128 * ROW_B)             // 18432
#define STAGE_B  (2 * TILE_B)              // 36864  (A1, B1)
#define SM_TOTAL (2 * STAGE_B)             // 73728

__global__ void __launch_bounds__(256, 2)
gemm_s8(const int8_t* __restrict__ A1, const int8_t* __restrict__ B1,
        float* __restrict__ C,
        const unsigned* __restrict__ maxA, const unsigned* __restrict__ maxB,
        float* __restrict__ out2, const float* __restrict__ bias2)
{
    extern __shared__ __align__(16) char smem[];
    const uint32_t sb = smem_u32(smem);
    const int tid  = threadIdx.x;
    const int wid  = tid >> 5, lane = tid & 31;
    const int wm   = wid & 1;
    const int wn   = wid >> 1;
    const int n0 = blockIdx.x * 128, b = blockIdx.y;

    const int8_t* tb[2] = {
        A1 + (size_t)n0 * NNODE,
        B1 + (size_t)b * NFEAT * NNODE };

    // cp.async plan: 2 tiles x 1024 chunks(16B) = 2048 / 256 thr = 8 each.
    const int c16   = (tid & 7) * 16;
    const int rbase = tid >> 3;            // 0..31

    const uint32_t offA = (uint32_t)(wm * 64 + (lane & 15)) * ROW_B + (lane >> 4) * 16;
    const uint32_t offB = (uint32_t)(wn * 32 + (lane & 7)) * ROW_B + ((lane >> 3) & 1) * 16;

    int p1[4][4][4];
    #pragma unroll
    for (int mi = 0; mi < 4; mi++)
        #pragma unroll
        for (int ni = 0; ni < 4; ni++)
            #pragma unroll
            for (int e = 0; e < 4; e++) p1[mi][ni][e] = 0;

    #pragma unroll
    for (int j = 0; j < 8; j++) {
        const int row = (j & 3) * 32 + rbase;
        CP16(sb + (j >> 2) * TILE_B + row * ROW_B + c16,
             tb[j >> 2] + (size_t)row * NNODE + c16);
    }
    CP_COMMIT();

    for (int i = 0; i < NSTAGE; i++) {
        const int buf = i & 1;
        if (i < NSTAGE - 1) {
            const uint32_t dbase = sb + (buf ^ 1) * STAGE_B;
            const int koff = (i + 1) * KC;
            #pragma unroll
            for (int j = 0; j < 8; j++) {
                const int row = (j & 3) * 32 + rbase;
                CP16(dbase + (j >> 2) * TILE_B + row * ROW_B + c16,
                     tb[j >> 2] + (size_t)row * NNODE + koff + c16);
            }
            CP_COMMIT();
            CP_WAIT1();
        } else {
            CP_WAIT0();
        }
        __syncthreads();

        const uint32_t s = sb + buf * STAGE_B;
        #pragma unroll
        for (int ks = 0; ks < 4; ks++) {
            uint32_t a1f[4][4];
            #pragma unroll
            for (int mi = 0; mi < 4; mi++) {
                const uint32_t a = s + offA + mi * (16 * ROW_B) + ks * 32;
                LDSM4(a1f[mi], a);
            }
            #pragma unroll
            for (int ni = 0; ni < 4; ni++) {
                uint32_t b1f[2];
                const uint32_t a = s + TILE_B + offB + ni * (8 * ROW_B) + ks * 32;
                LDSM2(b1f, a);
                #pragma unroll
                for (int mi = 0; mi < 4; mi++)
                    MMA_S8(p1[mi][ni], a1f[mi], b1f);
            }
        }
        __syncthreads();
    }

    const float mA = __uint_as_float(*maxA), mB = __uint_as_float(*maxB);
    const float s1 = (mA * mB) * (1.f / 16129.f);   // /127^2
    const int mrow = wm * 64 + (lane >> 2);
    const int ncol = wn * 32 + (lane & 3) * 2;

    if (out2 == nullptr) {
        float* Cb = C + ((size_t)b * NNODE + n0) * NFEAT;
        #pragma unroll
        for (int mi = 0; mi < 4; mi++) {
            #pragma unroll
            for (int ni = 0; ni < 4; ni++) {
                float* q0 = Cb + (size_t)(mrow + mi * 16) * NFEAT + ncol + ni * 8;
                float* qq = q0 + 8 * NFEAT;
                *(float2*)q0 = make_float2(s1 * (float)p1[mi][ni][0], s1 * (float)p1[mi][ni][1]);
                *(float2*)qq = make_float2(s1 * (float)p1[mi][ni][2], s1 * (float)p1[mi][ni][3]);
            }
        }
    } else {
        // fused bias + log_softmax epilogue: bounce acc through smem (stages dead)
        float* sm = (float*)smem;                       // [128][132] fp32 (67.6 KB <= 73.7)
        #pragma unroll
        for (int mi = 0; mi < 4; mi++) {
            #pragma unroll
            for (int ni = 0; ni < 4; ni++) {
                const int r0 = mrow + mi * 16, c0 = ncol + ni * 8;
                sm[r0 * 132 + c0]           = s1 * (float)p1[mi][ni][0];
                sm[r0 * 132 + c0 + 1]       = s1 * (float)p1[mi][ni][1];
                sm[(r0 + 8) * 132 + c0]     = s1 * (float)p1[mi][ni][2];
                sm[(r0 + 8) * 132 + c0 + 1] = s1 * (float)p1[mi][ni][3];
            }
        }
        __syncthreads();
        const float4 bb = ((const float4*)bias2)[lane];
        for (int rr = wid * 16; rr < wid * 16 + 16; rr++) {
            float4 v = *(float4*)&sm[rr * 132 + lane * 4];
            float v0 = v.x + bb.x, v1 = v.y + bb.y, v2 = v.z + bb.z, v3 = v.w + bb.w;
            float m = fmaxf(fmaxf(v0, v1), fmaxf(v2, v3));
            #pragma unroll
            for (int o = 16; o > 0; o >>= 1) m = fmaxf(m, __shfl_xor_sync(0xFFFFFFFFu, m, o));
            float ss = expf(v0 - m) + expf(v1 - m) + expf(v2 - m) + expf(v3 - m);
            #pragma unroll
            for (int o = 16; o > 0; o >>= 1) ss += __shfl_xor_sync(0xFFFFFFFFu, ss, o);
            const float lse = m + logf(ss);
            float4 o4; o4.x = v0 - lse; o4.y = v1 - lse; o4.z = v2 - lse; o4.w = v3 - lse;
            *(float4*)(out2 + ((size_t)b * NNODE + n0 + rr) * NFEAT + lane * 4) = o4;
        }
    }
}

// ---------------------------------------------------------------------------
// MLP on tensor cores (bf16 3-term split both layers) — unchanged from R11.
// Per CTA: 128 rows. A2T[b][w][n] = relu(T @ W1 + b1) @ W2, + global absmax.
// ---------------------------------------------------------------------------
#define MROWB 272                                      // 256B data + 16 pad
#define MLVL  (128 * MROWB)                            // 34816
#define M_RA  0
#define M_RB  (2 * MLVL)                               // 69632
#define M_RC  (4 * MLVL)                               // 139264
#define M_SM  (6 * MLVL)                               // 208896

__global__ void __launch_bounds__(256, 1)
mlp_tensor(const float* __restrict__ T,
           const __nv_bfloat16* __restrict__ W1Th, const __nv_bfloat16* __restrict__ W1Tl,
           const __nv_bfloat16* __restrict__ W2Th, const __nv_bfloat16* __restrict__ W2Tl,
           const float* __restrict__ b1,
           float* __restrict__ A2T, unsigned* __restrict__ mx)
{
    extern __shared__ __align__(16) char smem[];
    const uint32_t sb = smem_u32(smem);
    const int tid  = threadIdx.x;
    const int wid  = tid >> 5, lane = tid & 31;
    const int wm   = wid & 1, wn = wid >> 1;
    const size_t row0 = (size_t)blockIdx.x * 128;
    const int b     = (int)(row0 >> 12);
    const int nbase = (int)(row0 & 4095);

    // --- issue W1T half0 loads, then convert T while they fly ---
    {
        #pragma unroll
        for (int j = 0; j < 8; j++) {
            int cid = j * 256 + tid;         // 2048
            int r = cid >> 4, c = cid & 15;
            CP16(sb + M_RB + r * MROWB + c * 16,        W1Th + (size_t)r * NFEAT + c * 8);
            CP16(sb + M_RB + MLVL + r * MROWB + c * 16, W1Tl + (size_t)r * NFEAT + c * 8);
        }
        CP_COMMIT();
    }
    {
        const int r  = tid >> 1;
        const int wb = (tid & 1) * 64;
        const float* src = T + (row0 + r) * NFEAT + wb;
        #pragma unroll
        for (int i = 0; i < 16; i++) {
            float4 v = *(const float4*)(src + i * 4);
            unsigned short h0,l0,h1,l1,h2,l2,h3,l3;
            bf16split(v.x, h0, l0); bf16split(v.y, h1, l1);
            bf16split(v.z, h2, l2); bf16split(v.w, h3, l3);
            uint32_t hi01 = (uint32_t)h0 | ((uint32_t)h1 << 16);
            uint32_t hi23 = (uint32_t)h2 | ((uint32_t)h3 << 16);
            uint32_t lo01 = (uint32_t)l0 | ((uint32_t)l1 << 16);
            uint32_t lo23 = (uint32_t)l2 | ((uint32_t)l3 << 16);
            const uint32_t base = sb + M_RA + r * MROWB + (wb + i * 4) * 2;
            asm volatile("st.shared.u32 [%0], %1;" :: "r"(base),     "r"(hi01));
            asm volatile("st.shared.u32 [%0], %1;" :: "r"(base + 4), "r"(hi23));
            asm volatile("st.shared.u32 [%0], %1;" :: "r"(base + MLVL),     "r"(lo01));
            asm volatile("st.shared.u32 [%0], %1;" :: "r"(base + MLVL + 4), "r"(lo23));
        }
    }
    CP_WAIT0();
    __syncthreads();

    const uint32_t offA = (uint32_t)(wm * 64 + (lane & 15)) * MROWB + (lane >> 4) * 16;
    const uint32_t offB = (uint32_t)(wn * 32 + (lane & 7)) * MROWB + ((lane >> 3) & 1) * 16;

    float acc2[4][4][4];
    #pragma unroll
    for (int mi = 0; mi < 4; mi++)
        #pragma unroll
        for (int ni = 0; ni < 4; ni++)
            #pragma unroll
            for (int e = 0; e < 4; e++) acc2[mi][ni][e] = 0.f;

    #pragma unroll 1
    for (int half = 0; half < 2; half++) {
        // ---- layer 1 half: h[:, half*128 .. half*128+127] = T @ W1T-half ----
        float acc1[4][4][4];
        #pragma unroll
        for (int mi = 0; mi < 4; mi++)
            #pragma unroll
            for (int ni = 0; ni < 4; ni++)
                #pragma unroll
                for (int e = 0; e < 4; e++) acc1[mi][ni][e] = 0.f;

        #pragma unroll
        for (int ks = 0; ks < 8; ks++) {
            uint32_t ah[4][4], al[4][4];
            #pragma unroll
            for (int mi = 0; mi < 4; mi++) {
                const uint32_t a = sb + M_RA + offA + mi * (16 * MROWB) + ks * 32;
                LDSM4(ah[mi], a);
                LDSM4(al[mi], a + MLVL);
            }
            #pragma unroll
            for (int ni = 0; ni < 4; ni++) {
                uint32_t bh[2], bl[2];
                const uint32_t a = sb + M_RB + offB + ni * (8 * MROWB) + ks * 32;
                LDSM2(bh, a);
                LDSM2(bl, a + MLVL);
                #pragma unroll
                for (int mi = 0; mi < 4; mi++) {
                    MMA_BF16(acc1[mi][ni], ah[mi], bh);
                    MMA_BF16(acc1[mi][ni], ah[mi], bl);
                    MMA_BF16(acc1[mi][ni], al[mi], bh);
                }
            }
        }
        __syncthreads();                     // everyone done reading RB

        // load W2T half into RB
        #pragma unroll
        for (int j = 0; j < 8; j++) {
            int cid = j * 256 + tid;
            int r = cid >> 4, c = cid & 15;
            CP16(sb + M_RB + r * MROWB + c * 16,
                 W2Th + (size_t)r * NHID + half * 128 + c * 8);
            CP16(sb + M_RB + MLVL + r * MROWB + c * 16,
                 W2Tl + (size_t)r * NHID + half * 128 + c * 8);
        }
        CP_COMMIT();

        // relu + bias + bf16 split h -> RC (overlaps with W2T copy)
        {
            const int cb = wn * 32 + (lane & 3) * 2;
            #pragma unroll
            for (int ni = 0; ni < 4; ni++) {
                const float2 bv = *(const float2*)(b1 + half * 128 + cb + ni * 8);
                #pragma unroll
                for (int mi = 0; mi < 4; mi++) {
                    const int r = wm * 64 + (lane >> 2) + mi * 16;
                    float h0 = fmaxf(acc1[mi][ni][0] + bv.x, 0.f);
                    float h1 = fmaxf(acc1[mi][ni][1] + bv.y, 0.f);
                    float h2 = fmaxf(acc1[mi][ni][2] + bv.x, 0.f);
                    float h3 = fmaxf(acc1[mi][ni][3] + bv.y, 0.f);
                    unsigned short a0,a1,a2,a3,b0,bb1,b2q,b3;
                    bf16split(h0, a0, b0); bf16split(h1, a1, bb1);
                    bf16split(h2, a2, b2q); bf16split(h3, a3, b3);
                    const uint32_t c2 = (cb + ni * 8) * 2;
                    uint32_t ad0 = sb + M_RC + r * MROWB + c2;
                    uint32_t ad1 = sb + M_RC + (r + 8) * MROWB + c2;
                    uint32_t hi0 = (uint32_t)a0 | ((uint32_t)a1 << 16);
                    uint32_t hi1 = (uint32_t)a2 | ((uint32_t)a3 << 16);
                    uint32_t lo0 = (uint32_t)b0 | ((uint32_t)bb1 << 16);
                    uint32_t lo1 = (uint32_t)b2q | ((uint32_t)b3 << 16);
                    asm volatile("st.shared.u32 [%0], %1;" :: "r"(ad0), "r"(hi0));
                    asm volatile("st.shared.u32 [%0], %1;" :: "r"(ad1), "r"(hi1));
                    asm volatile("st.shared.u32 [%0], %1;" :: "r"(ad0 + MLVL), "r"(lo0));
                    asm volatile("st.shared.u32 [%0], %1;" :: "r"(ad1 + MLVL), "r"(lo1));
                }
            }
        }
        CP_WAIT0();
        __syncthreads();                     // h + W2T half ready

        // ---- layer 2 half: acc2 += h_half @ W2T-half ----
        #pragma unroll
        for (int ks = 0; ks < 8; ks++) {
            uint32_t ah[4][4], al[4][4];
            #pragma unroll
            for (int mi = 0; mi < 4; mi++) {
                const uint32_t a = sb + M_RC + offA + mi * (16 * MROWB) + ks * 32;
                LDSM4(ah[mi], a);
                LDSM4(al[mi], a + MLVL);
            }
            #pragma unroll
            for (int ni = 0; ni < 4; ni++) {
                uint32_t bh[2], bl[2];
                const uint32_t a = sb + M_RB + offB + ni * (8 * MROWB) + ks * 32;
                LDSM2(bh, a);
                LDSM2(bl, a + MLVL);
                #pragma unroll
                for (int mi = 0; mi < 4; mi++) {
                    MMA_BF16(acc2[mi][ni], ah[mi], bh);
                    MMA_BF16(acc2[mi][ni], ah[mi], bl);
                    MMA_BF16(acc2[mi][ni], al[mi], bh);
                }
            }
        }
        if (half == 0) {
            __syncthreads();                 // done reading RB; reload W1T half1
            #pragma unroll
            for (int j = 0; j < 8; j++) {
                int cid = j * 256 + tid;
                int r = cid >> 4, c = cid & 15;
                CP16(sb + M_RB + r * MROWB + c * 16,
                     W1Th + (size_t)(128 + r) * NFEAT + c * 8);
                CP16(sb + M_RB + MLVL + r * MROWB + c * 16,
                     W1Tl + (size_t)(128 + r) * NFEAT + c * 8);
            }
            CP_COMMIT();
            CP_WAIT0();
            __syncthreads();
        }
    }

    // ---- epilogue: transpose via smem (RA/RB dead), write A2T + absmax ----
    __syncthreads();
    float* sm = (float*)smem;                // [128][132] fp32 in RA+RB space
    {
        const int mrow = wm * 64 + (lane >> 2);
        const int ncol = wn * 32 + (lane & 3) * 2;
        #pragma unroll
        for (int mi = 0; mi < 4; mi++)
            #pragma unroll
            for (int ni = 0; ni < 4; ni++) {
                const int r0 = mrow + mi * 16, c0 = ncol + ni * 8;
                sm[r0 * 132 + c0]           = acc2[mi][ni][0];
                sm[r0 * 132 + c0 + 1]       = acc2[mi][ni][1];
                sm[(r0 + 8) * 132 + c0]     = acc2[mi][ni][2];
                sm[(r0 + 8) * 132 + c0 + 1] = acc2[mi][ni][3];
            }
    }
    __syncthreads();
    {
        const int w  = tid & 127;
        const int nh = (tid >> 7) * 64;
        float lm = 0.f;
        float* dst = A2T + ((size_t)b * NFEAT + w) * NNODE + nbase + nh;
        #pragma unroll
        for (int g = 0; g < 16; g++) {
            float4 v;
            v.x = sm[(nh + g * 4 + 0) * 132 + w];
            v.y = sm[(nh + g * 4 + 1) * 132 + w];
            v.z = sm[(nh + g * 4 + 2) * 132 + w];
            v.w = sm[(nh + g * 4 + 3) * 132 + w];
            lm = fmaxf(lm, fmaxf(fmaxf(fabsf(v.x), fabsf(v.y)), fmaxf(fabsf(v.z), fabsf(v.w))));
            *(float4*)(dst + g * 4) = v;
        }
        #pragma unroll
        for (int o = 16; o > 0; o >>= 1) lm = fmaxf(lm, __shfl_xor_sync(0xFFFFFFFFu, lm, o));
        __shared__ float red[8];
        if ((tid & 31) == 0) red[tid >> 5] = lm;
        __syncthreads();
        if (tid == 0) {
            float bm = red[0];
            #pragma unroll
            for (int i = 1; i < 8; i++) bm = fmaxf(bm, red[i]);
            atomicMax(mx, __float_as_uint(bm));
        }
    }
}

// ---------------------------------------------------------------------------
// Launch sequence
// ---------------------------------------------------------------------------
extern "C" void kernel_launch(void* const* d_in, const int* in_sizes, int n_in,
                              void* d_out, int out_size)
{
    const float* x   = (const float*)d_in[0];
    const float* adj = (const float*)d_in[1];
    const float* W1  = (const float*)d_in[2];
    const float* b1  = (const float*)d_in[3];
    const float* W2  = (const float*)d_in[4];
    const float* b2  = (const float*)d_in[5];
    float* out = (float*)d_out;

    int8_t *pA1, *pB1; float *pT, *pM; unsigned* pS;
    __nv_bfloat16 *pW1h, *pW1l, *pW2h, *pW2l;
    cudaGetSymbolAddress((void**)&pA1, g_A1);
    cudaGetSymbolAddress((void**)&pB1, g_B1);
    cudaGetSymbolAddress((void**)&pT,  g_T);
    cudaGetSymbolAddress((void**)&pM,  g_A2T);
    cudaGetSymbolAddress((void**)&pS,  g_scal);
    cudaGetSymbolAddress((void**)&pW1h, g_W1Th);
    cudaGetSymbolAddress((void**)&pW1l, g_W1Tl);
    cudaGetSymbolAddress((void**)&pW2h, g_W2Th);
    cudaGetSymbolAddress((void**)&pW2l, g_W2Tl);

    cudaFuncSetAttribute(gemm_s8,    cudaFuncAttributeMaxDynamicSharedMemorySize, SM_TOTAL);
    cudaFuncSetAttribute(mlp_tensor, cudaFuncAttributeMaxDynamicSharedMemorySize, M_SM);

    const size_t nadj = (size_t)NNODE * NNODE;              // 16.8M
    const size_t nx   = (size_t)BATCH * NNODE * NFEAT;      // 33.5M
    const dim3 ggrid(NNODE / 128, BATCH);                   // 32 x 64
    const int  nrows = BATCH * NNODE;                       // 262144

    // scales
    zero_scal<<<1, 1>>>(pS);
    rmax4<<<2048, 256>>>((const float4*)adj, (int)(nadj / 4), pS + 0);
    rmax4<<<2048, 256>>>((const float4*)x,   (int)(nx / 4),   pS + 1);

    // quantize inputs + weight prep
    quant1_pt<<<(unsigned)(nadj / (256 * 4)), 256>>>(adj, pA1, pS + 0);
    quant_xT<<<dim3(NNODE / 32, NFEAT / 32, BATCH), dim3(32, 8)>>>(x, pB1, pS + 1);
    wprep1<<<NHID * NFEAT / 256, 256>>>(W1, pW1h, pW1l);
    wprep2<<<NFEAT * NHID / 256, 256>>>(W2, pW2h, pW2l);

    // K1: T = adj @ x
    gemm_s8<<<ggrid, 256, SM_TOTAL>>>(pA1, pB1, pT, pS + 0, pS + 1,
                                      nullptr, nullptr);
    // K2: A2T = relu(T@W1+b1)@W2 (tensor-core), transposed + absmax
    mlp_tensor<<<nrows / 128, 256, M_SM>>>(pT, pW1h, pW1l, pW2h, pW2l, b1, pM, pS + 2);
    // quantize MLP output (already [b][w][n])
    quant1_pt<<<(unsigned)(nx / (256 * 4)), 256>>>(pM, pB1, pS + 2);
    // K3 + fused bias/log_softmax -> out
    gemm_s8<<<ggrid, 256, SM_TOTAL>>>(pA1, pB1, nullptr, pS + 0, pS + 2,
                                      out, b2);

    (void)in_sizes; (void)n_in; (void)out_size;
}

// round 15
// speedup vs baseline: 2.5266x; 1.1953x over previous
#include <cuda_runtime.h>
#include <cuda_bf16.h>
#include <math.h>
#include <stdint.h>

// Problem dims (fixed by reference)
#define BATCH   64          // B*L
#define NNODE   4096        // H
#define NFEAT   128         // W == nclass
#define NHID    256

// ---------------------------------------------------------------------------
// Static device scratch (no allocations allowed)
// ---------------------------------------------------------------------------
__device__ int8_t g_A1 [(size_t)NNODE * NNODE];                  // adj int8
__device__ int8_t g_B1 [(size_t)BATCH * NFEAT * NNODE];          // B int8 [b][w][k]
__device__ __nv_bfloat16 g_Tb[(size_t)BATCH * NNODE * NFEAT];    // GEMM1 out (bf16)
__device__ float  g_A2T[(size_t)BATCH * NFEAT * NNODE];          // MLP out transposed
__device__ unsigned g_scal[3];                                   // absmax: adj, x, mlp
__device__ __nv_bfloat16 g_W1T[NHID * NFEAT];                    // W1^T bf16 [256][128]
__device__ __nv_bfloat16 g_W2T[NFEAT * NHID];                    // W2^T bf16 [128][256]

// ---------------------------------------------------------------------------
// PTX helpers (sm_80-era: ldmatrix / mma.sync / cp.async)
// ---------------------------------------------------------------------------
__device__ __forceinline__ uint32_t smem_u32(const void* p) {
    uint32_t a;
    asm("{ .reg .u64 t; cvta.to.shared.u64 t, %1; cvt.u32.u64 %0, t; }" : "=r"(a) : "l"(p));
    return a;
}

#define LDSM4(r, a)                                                                 \
    asm volatile("ldmatrix.sync.aligned.m8n8.x4.shared.b16 {%0,%1,%2,%3}, [%4];"    \
        : "=r"((r)[0]), "=r"((r)[1]), "=r"((r)[2]), "=r"((r)[3]) : "r"(a))

#define LDSM2(r, a)                                                                 \
    asm volatile("ldmatrix.sync.aligned.m8n8.x2.shared.b16 {%0,%1}, [%2];"          \
        : "=r"((r)[0]), "=r"((r)[1]) : "r"(a))

#define MMA_S8(c, a, bb)                                                            \
    asm volatile("mma.sync.aligned.m16n8k32.row.col.s32.s8.s8.s32 "                 \
        "{%0,%1,%2,%3}, {%4,%5,%6,%7}, {%8,%9}, {%0,%1,%2,%3};"                     \
        : "+r"((c)[0]), "+r"((c)[1]), "+r"((c)[2]), "+r"((c)[3])                    \
        : "r"((a)[0]), "r"((a)[1]), "r"((a)[2]), "r"((a)[3]),                       \
          "r"((bb)[0]), "r"((bb)[1]))

#define MMA_BF16(c, a, bb)                                                          \
    asm volatile("mma.sync.aligned.m16n8k16.row.col.f32.bf16.bf16.f32 "             \
        "{%0,%1,%2,%3}, {%4,%5,%6,%7}, {%8,%9}, {%0,%1,%2,%3};"                     \
        : "+f"((c)[0]), "+f"((c)[1]), "+f"((c)[2]), "+f"((c)[3])                    \
        : "r"((a)[0]), "r"((a)[1]), "r"((a)[2]), "r"((a)[3]),                       \
          "r"((bb)[0]), "r"((bb)[1]))

#define CP16(dst, src) asm volatile("cp.async.cg.shared.global [%0], [%1], 16;" :: "r"(dst), "l"(src) : "memory")
#define CP_COMMIT()    asm volatile("cp.async.commit_group;" ::: "memory")
#define CP_WAIT1()     asm volatile("cp.async.wait_group 1;" ::: "memory")
#define CP_WAIT0()     asm volatile("cp.async.wait_group 0;" ::: "memory")

__device__ __forceinline__ int q1(float v, float inv) {
    return (int)fminf(127.f, fmaxf(-127.f, rintf(v * inv)));
}

__device__ __forceinline__ uint32_t packbf2(float a, float b) {
    return (uint32_t)__bfloat16_as_ushort(__float2bfloat16_rn(a)) |
           ((uint32_t)__bfloat16_as_ushort(__float2bfloat16_rn(b)) << 16);
}

// ---------------------------------------------------------------------------
// tiny kernels
// ---------------------------------------------------------------------------
__global__ void zero_scal(unsigned* s) { s[0] = 0u; s[1] = 0u; s[2] = 0u; }

__global__ void __launch_bounds__(256)
rmax4(const float4* __restrict__ p, int n4, unsigned* out)
{
    float m = 0.f;
    for (int i = blockIdx.x * blockDim.x + threadIdx.x; i < n4; i += gridDim.x * blockDim.x) {
        float4 v = p[i];
        m = fmaxf(m, fmaxf(fmaxf(fabsf(v.x), fabsf(v.y)), fmaxf(fabsf(v.z), fabsf(v.w))));
    }
    #pragma unroll
    for (int o = 16; o > 0; o >>= 1) m = fmaxf(m, __shfl_xor_sync(0xFFFFFFFFu, m, o));
    __shared__ float red[8];
    if ((threadIdx.x & 31) == 0) red[threadIdx.x >> 5] = m;
    __syncthreads();
    if (threadIdx.x == 0) {
        float b = red[0];
        #pragma unroll
        for (int i = 1; i < 8; i++) b = fmaxf(b, red[i]);
        atomicMax(out, __float_as_uint(b));
    }
}

// weight transpose + bf16 prep (single level)
__global__ void __launch_bounds__(256)
wprep1(const float* __restrict__ W1, __nv_bfloat16* __restrict__ h)
{
    int gid = blockIdx.x * 256 + threadIdx.x;           // 32768
    int r = gid >> 7, c = gid & 127;                    // out [256][128]
    h[gid] = __float2bfloat16_rn(W1[(size_t)c * NHID + r]);
}
__global__ void __launch_bounds__(256)
wprep2(const float* __restrict__ W2, __nv_bfloat16* __restrict__ h)
{
    int gid = blockIdx.x * 256 + threadIdx.x;           // 32768
    int r = gid >> 8, c = gid & 255;                    // out [128][256]
    h[gid] = __float2bfloat16_rn(W2[(size_t)c * NFEAT + r]);
}

// ---------------------------------------------------------------------------
// single-level quantize (adj, and MLP output which is already [b][w][n])
// ---------------------------------------------------------------------------
__global__ void __launch_bounds__(256)
quant1_pt(const float* __restrict__ src, int8_t* __restrict__ d1,
          const unsigned* __restrict__ mx)
{
    const float inv = 127.f / fmaxf(__uint_as_float(*mx), 1e-30f);
    const size_t i = ((size_t)blockIdx.x * 256 + threadIdx.x) * 4;
    float4 v = *(const float4*)(src + i);
    *(char4*)(d1 + i) = make_char4((char)q1(v.x, inv), (char)q1(v.y, inv),
                                   (char)q1(v.z, inv), (char)q1(v.w, inv));
}

// ---------------------------------------------------------------------------
// x [b][n][w] fp32 -> int8 transposed [b][w][n]
// ---------------------------------------------------------------------------
__global__ void __launch_bounds__(256)
quant_xT(const float* __restrict__ x, int8_t* __restrict__ d1,
         const unsigned* __restrict__ mx)
{
    __shared__ float t[32][33];
    const float inv = 127.f / fmaxf(__uint_as_float(*mx), 1e-30f);
    const int tx = threadIdx.x, ty = threadIdx.y;       // 32 x 8
    const int n0 = blockIdx.x * 32, w0 = blockIdx.y * 32, b = blockIdx.z;
    #pragma unroll
    for (int j = 0; j < 4; j++) {
        int n = n0 + ty + j * 8;
        t[ty + j * 8][tx] = x[((size_t)b * NNODE + n) * NFEAT + w0 + tx];
    }
    __syncthreads();
    #pragma unroll
    for (int j = 0; j < 4; j++) {
        int w = w0 + ty + j * 8;
        size_t o = ((size_t)b * NFEAT + w) * NNODE + n0 + tx;
        d1[o] = (int8_t)q1(t[tx][ty + j * 8], inv);
    }
}

// ---------------------------------------------------------------------------
// int8 single-level GEMM: C[b][n][w] = s1 * sum_k a1[n,k]*b1[w,k]
// GEMM1 mode (out2==null): writes bf16 into Cb16.
// GEMM2 mode (out2!=null): fused bias + log_softmax epilogue -> out2.
// 256 thr, warp tile 64x32, 2 CTAs/SM.
// ---------------------------------------------------------------------------
#define KC       128
#define NSTAGE   (NNODE / KC)              // 32
#define ROW_B    144
#define TILE_B   (128 * ROW_B)             // 18432
#define STAGE_B  (2 * TILE_B)              // 36864  (A1, B1)
#define SM_TOTAL (2 * STAGE_B)             // 73728

__global__ void __launch_bounds__(256, 2)
gemm_s8(const int8_t* __restrict__ A1, const int8_t* __restrict__ B1,
        __nv_bfloat16* __restrict__ Cb16,
        const unsigned* __restrict__ maxA, const unsigned* __restrict__ maxB,
        float* __restrict__ out2, const float* __restrict__ bias2)
{
    extern __shared__ __align__(16) char smem[];
    const uint32_t sb = smem_u32(smem);
    const int tid  = threadIdx.x;
    const int wid  = tid >> 5, lane = tid & 31;
    const int wm   = wid & 1;
    const int wn   = wid >> 1;
    const int n0 = blockIdx.x * 128, b = blockIdx.y;

    const int8_t* tb[2] = {
        A1 + (size_t)n0 * NNODE,
        B1 + (size_t)b * NFEAT * NNODE };

    const int c16   = (tid & 7) * 16;
    const int rbase = tid >> 3;            // 0..31

    const uint32_t offA = (uint32_t)(wm * 64 + (lane & 15)) * ROW_B + (lane >> 4) * 16;
    const uint32_t offB = (uint32_t)(wn * 32 + (lane & 7)) * ROW_B + ((lane >> 3) & 1) * 16;

    int p1[4][4][4];
    #pragma unroll
    for (int mi = 0; mi < 4; mi++)
        #pragma unroll
        for (int ni = 0; ni < 4; ni++)
            #pragma unroll
            for (int e = 0; e < 4; e++) p1[mi][ni][e] = 0;

    #pragma unroll
    for (int j = 0; j < 8; j++) {
        const int row = (j & 3) * 32 + rbase;
        CP16(sb + (j >> 2) * TILE_B + row * ROW_B + c16,
             tb[j >> 2] + (size_t)row * NNODE + c16);
    }
    CP_COMMIT();

    for (int i = 0; i < NSTAGE; i++) {
        const int buf = i & 1;
        if (i < NSTAGE - 1) {
            const uint32_t dbase = sb + (buf ^ 1) * STAGE_B;
            const int koff = (i + 1) * KC;
            #pragma unroll
            for (int j = 0; j < 8; j++) {
                const int row = (j & 3) * 32 + rbase;
                CP16(dbase + (j >> 2) * TILE_B + row * ROW_B + c16,
                     tb[j >> 2] + (size_t)row * NNODE + koff + c16);
            }
            CP_COMMIT();
            CP_WAIT1();
        } else {
            CP_WAIT0();
        }
        __syncthreads();

        const uint32_t s = sb + buf * STAGE_B;
        #pragma unroll
        for (int ks = 0; ks < 4; ks++) {
            uint32_t a1f[4][4];
            #pragma unroll
            for (int mi = 0; mi < 4; mi++) {
                const uint32_t a = s + offA + mi * (16 * ROW_B) + ks * 32;
                LDSM4(a1f[mi], a);
            }
            #pragma unroll
            for (int ni = 0; ni < 4; ni++) {
                uint32_t b1f[2];
                const uint32_t a = s + TILE_B + offB + ni * (8 * ROW_B) + ks * 32;
                LDSM2(b1f, a);
                #pragma unroll
                for (int mi = 0; mi < 4; mi++)
                    MMA_S8(p1[mi][ni], a1f[mi], b1f);
            }
        }
        __syncthreads();
    }

    const float mA = __uint_as_float(*maxA), mB = __uint_as_float(*maxB);
    const float s1 = (mA * mB) * (1.f / 16129.f);   // /127^2
    const int mrow = wm * 64 + (lane >> 2);
    const int ncol = wn * 32 + (lane & 3) * 2;

    if (out2 == nullptr) {
        // bf16 output (feeds mlp_tensor directly)
        __nv_bfloat16* Cb = Cb16 + ((size_t)b * NNODE + n0) * NFEAT;
        #pragma unroll
        for (int mi = 0; mi < 4; mi++) {
            #pragma unroll
            for (int ni = 0; ni < 4; ni++) {
                const size_t i0 = (size_t)(mrow + mi * 16) * NFEAT + ncol + ni * 8;
                *(uint32_t*)(Cb + i0) =
                    packbf2(s1 * (float)p1[mi][ni][0], s1 * (float)p1[mi][ni][1]);
                *(uint32_t*)(Cb + i0 + 8 * NFEAT) =
                    packbf2(s1 * (float)p1[mi][ni][2], s1 * (float)p1[mi][ni][3]);
            }
        }
    } else {
        // fused bias + log_softmax epilogue: bounce acc through smem (stages dead)
        float* sm = (float*)smem;                       // [128][132] fp32 (67.6 KB <= 73.7)
        #pragma unroll
        for (int mi = 0; mi < 4; mi++) {
            #pragma unroll
            for (int ni = 0; ni < 4; ni++) {
                const int r0 = mrow + mi * 16, c0 = ncol + ni * 8;
                sm[r0 * 132 + c0]           = s1 * (float)p1[mi][ni][0];
                sm[r0 * 132 + c0 + 1]       = s1 * (float)p1[mi][ni][1];
                sm[(r0 + 8) * 132 + c0]     = s1 * (float)p1[mi][ni][2];
                sm[(r0 + 8) * 132 + c0 + 1] = s1 * (float)p1[mi][ni][3];
            }
        }
        __syncthreads();
        const float4 bb = ((const float4*)bias2)[lane];
        for (int rr = wid * 16; rr < wid * 16 + 16; rr++) {
            float4 v = *(float4*)&sm[rr * 132 + lane * 4];
            float v0 = v.x + bb.x, v1 = v.y + bb.y, v2 = v.z + bb.z, v3 = v.w + bb.w;
            float m = fmaxf(fmaxf(v0, v1), fmaxf(v2, v3));
            #pragma unroll
            for (int o = 16; o > 0; o >>= 1) m = fmaxf(m, __shfl_xor_sync(0xFFFFFFFFu, m, o));
            float ss = expf(v0 - m) + expf(v1 - m) + expf(v2 - m) + expf(v3 - m);
            #pragma unroll
            for (int o = 16; o > 0; o >>= 1) ss += __shfl_xor_sync(0xFFFFFFFFu, ss, o);
            const float lse = m + logf(ss);
            float4 o4; o4.x = v0 - lse; o4.y = v1 - lse; o4.z = v2 - lse; o4.w = v3 - lse;
            *(float4*)(out2 + ((size_t)b * NNODE + n0 + rr) * NFEAT + lane * 4) = o4;
        }
    }
}

// ---------------------------------------------------------------------------
// MLP on tensor cores — single bf16 (no split). Per CTA: 128 rows.
// A2T[b][w][n] = relu(T @ W1 + b1) @ W2, + global absmax.
// smem regions (one level each): RA = T rows, RB = W half, RC = h half.
// ---------------------------------------------------------------------------
#define MROWB 272                                      // 256B data + 16 pad
#define MTILE (128 * MROWB)                            // 34816
#define M_RA  0
#define M_RB  MTILE                                    // 34816
#define M_RC  (2 * MTILE)                              // 69632
#define M_SM  (3 * MTILE)                              // 104448  (fp32 bounce 67.6K fits)

__global__ void __launch_bounds__(256, 1)
mlp_tensor(const __nv_bfloat16* __restrict__ Tb,
           const __nv_bfloat16* __restrict__ W1T,
           const __nv_bfloat16* __restrict__ W2T,
           const float* __restrict__ b1,
           float* __restrict__ A2T, unsigned* __restrict__ mx)
{
    extern __shared__ __align__(16) char smem[];
    const uint32_t sb = smem_u32(smem);
    const int tid  = threadIdx.x;
    const int wid  = tid >> 5, lane = tid & 31;
    const int wm   = wid & 1, wn = wid >> 1;
    const size_t row0 = (size_t)blockIdx.x * 128;
    const int b     = (int)(row0 >> 12);
    const int nbase = (int)(row0 & 4095);

    // --- load T rows (bf16, direct) + W1T half0, one commit group ---
    #pragma unroll
    for (int j = 0; j < 8; j++) {
        int cid = j * 256 + tid;             // 2048 chunks: r=cid>>4 (0..127), c=cid&15
        int r = cid >> 4, c = cid & 15;
        CP16(sb + M_RA + r * MROWB + c * 16, Tb + (row0 + r) * NFEAT + c * 8);
        CP16(sb + M_RB + r * MROWB + c * 16, W1T + (size_t)r * NFEAT + c * 8);
    }
    CP_COMMIT();
    CP_WAIT0();
    __syncthreads();

    const uint32_t offA = (uint32_t)(wm * 64 + (lane & 15)) * MROWB + (lane >> 4) * 16;
    const uint32_t offB = (uint32_t)(wn * 32 + (lane & 7)) * MROWB + ((lane >> 3) & 1) * 16;

    float acc2[4][4][4];
    #pragma unroll
    for (int mi = 0; mi < 4; mi++)
        #pragma unroll
        for (int ni = 0; ni < 4; ni++)
            #pragma unroll
            for (int e = 0; e < 4; e++) acc2[mi][ni][e] = 0.f;

    #pragma unroll 1
    for (int half = 0; half < 2; half++) {
        // ---- layer 1 half: h[:, half*128 .. +127] = T @ W1T-half ----
        float acc1[4][4][4];
        #pragma unroll
        for (int mi = 0; mi < 4; mi++)
            #pragma unroll
            for (int ni = 0; ni < 4; ni++)
                #pragma unroll
                for (int e = 0; e < 4; e++) acc1[mi][ni][e] = 0.f;

        #pragma unroll
        for (int ks = 0; ks < 8; ks++) {
            uint32_t ah[4][4];
            #pragma unroll
            for (int mi = 0; mi < 4; mi++)
                LDSM4(ah[mi], sb + M_RA + offA + mi * (16 * MROWB) + ks * 32);
            #pragma unroll
            for (int ni = 0; ni < 4; ni++) {
                uint32_t bh[2];
                LDSM2(bh, sb + M_RB + offB + ni * (8 * MROWB) + ks * 32);
                #pragma unroll
                for (int mi = 0; mi < 4; mi++)
                    MMA_BF16(acc1[mi][ni], ah[mi], bh);
            }
        }
        __syncthreads();                     // done reading RB

        // load W2T half into RB
        #pragma unroll
        for (int j = 0; j < 8; j++) {
            int cid = j * 256 + tid;
            int r = cid >> 4, c = cid & 15;
            CP16(sb + M_RB + r * MROWB + c * 16,
                 W2T + (size_t)r * NHID + half * 128 + c * 8);
        }
        CP_COMMIT();

        // relu + bias + bf16 h -> RC (overlaps with W2T copy)
        {
            const int cb = wn * 32 + (lane & 3) * 2;
            #pragma unroll
            for (int ni = 0; ni < 4; ni++) {
                const float2 bv = *(const float2*)(b1 + half * 128 + cb + ni * 8);
                #pragma unroll
                for (int mi = 0; mi < 4; mi++) {
                    const int r = wm * 64 + (lane >> 2) + mi * 16;
                    const uint32_t c2 = (cb + ni * 8) * 2;
                    uint32_t v0 = packbf2(fmaxf(acc1[mi][ni][0] + bv.x, 0.f),
                                          fmaxf(acc1[mi][ni][1] + bv.y, 0.f));
                    uint32_t v1 = packbf2(fmaxf(acc1[mi][ni][2] + bv.x, 0.f),
                                          fmaxf(acc1[mi][ni][3] + bv.y, 0.f));
                    asm volatile("st.shared.u32 [%0], %1;"
                                 :: "r"(sb + M_RC + r * MROWB + c2), "r"(v0));
                    asm volatile("st.shared.u32 [%0], %1;"
                                 :: "r"(sb + M_RC + (r + 8) * MROWB + c2), "r"(v1));
                }
            }
        }
        CP_WAIT0();
        __syncthreads();                     // h + W2T half ready

        // ---- layer 2 half: acc2 += h_half @ W2T-half ----
        #pragma unroll
        for (int ks = 0; ks < 8; ks++) {
            uint32_t ah[4][4];
            #pragma unroll
            for (int mi = 0; mi < 4; mi++)
                LDSM4(ah[mi], sb + M_RC + offA + mi * (16 * MROWB) + ks * 32);
            #pragma unroll
            for (int ni = 0; ni < 4; ni++) {
                uint32_t bh[2];
                LDSM2(bh, sb + M_RB + offB + ni * (8 * MROWB) + ks * 32);
                #pragma unroll
                for (int mi = 0; mi < 4; mi++)
                    MMA_BF16(acc2[mi][ni], ah[mi], bh);
            }
        }
        if (half == 0) {
            __syncthreads();                 // done reading RB; reload W1T half1
            #pragma unroll
            for (int j = 0; j < 8; j++) {
                int cid = j * 256 + tid;
                int r = cid >> 4, c = cid & 15;
                CP16(sb + M_RB + r * MROWB + c * 16,
                     W1T + (size_t)(128 + r) * NFEAT + c * 8);
            }
            CP_COMMIT();
            CP_WAIT0();
            __syncthreads();
        }
    }

    // ---- epilogue: transpose via smem (RA/RB dead), write A2T + absmax ----
    __syncthreads();
    float* sm = (float*)smem;                // [128][132] fp32 in RA+RB space
    {
        const int mrow = wm * 64 + (lane >> 2);
        const int ncol = wn * 32 + (lane & 3) * 2;
        #pragma unroll
        for (int mi = 0; mi < 4; mi++)
            #pragma unroll
            for (int ni = 0; ni < 4; ni++) {
                const int r0 = mrow + mi * 16, c0 = ncol + ni * 8;
                sm[r0 * 132 + c0]           = acc2[mi][ni][0];
                sm[r0 * 132 + c0 + 1]       = acc2[mi][ni][1];
                sm[(r0 + 8) * 132 + c0]     = acc2[mi][ni][2];
                sm[(r0 + 8) * 132 + c0 + 1] = acc2[mi][ni][3];
            }
    }
    __syncthreads();
    {
        const int w  = tid & 127;
        const int nh = (tid >> 7) * 64;
        float lm = 0.f;
        float* dst = A2T + ((size_t)b * NFEAT + w) * NNODE + nbase + nh;
        #pragma unroll
        for (int g = 0; g < 16; g++) {
            float4 v;
            v.x = sm[(nh + g * 4 + 0) * 132 + w];
            v.y = sm[(nh + g * 4 + 1) * 132 + w];
            v.z = sm[(nh + g * 4 + 2) * 132 + w];
            v.w = sm[(nh + g * 4 + 3) * 132 + w];
            lm = fmaxf(lm, fmaxf(fmaxf(fabsf(v.x), fabsf(v.y)), fmaxf(fabsf(v.z), fabsf(v.w))));
            *(float4*)(dst + g * 4) = v;
        }
        #pragma unroll
        for (int o = 16; o > 0; o >>= 1) lm = fmaxf(lm, __shfl_xor_sync(0xFFFFFFFFu, lm, o));
        __shared__ float red[8];
        if ((tid & 31) == 0) red[tid >> 5] = lm;
        __syncthreads();
        if (tid == 0) {
            float bm = red[0];
            #pragma unroll
            for (int i = 1; i < 8; i++) bm = fmaxf(bm, red[i]);
            atomicMax(mx, __float_as_uint(bm));
        }
    }
}

// ---------------------------------------------------------------------------
// Launch sequence
// ---------------------------------------------------------------------------
extern "C" void kernel_launch(void* const* d_in, const int* in_sizes, int n_in,
                              void* d_out, int out_size)
{
    const float* x   = (const float*)d_in[0];
    const float* adj = (const float*)d_in[1];
    const float* W1  = (const float*)d_in[2];
    const float* b1  = (const float*)d_in[3];
    const float* W2  = (const float*)d_in[4];
    const float* b2  = (const float*)d_in[5];
    float* out = (float*)d_out;

    int8_t *pA1, *pB1; float *pM; unsigned* pS;
    __nv_bfloat16 *pTb, *pW1, *pW2;
    cudaGetSymbolAddress((void**)&pA1, g_A1);
    cudaGetSymbolAddress((void**)&pB1, g_B1);
    cudaGetSymbolAddress((void**)&pTb, g_Tb);
    cudaGetSymbolAddress((void**)&pM,  g_A2T);
    cudaGetSymbolAddress((void**)&pS,  g_scal);
    cudaGetSymbolAddress((void**)&pW1, g_W1T);
    cudaGetSymbolAddress((void**)&pW2, g_W2T);

    cudaFuncSetAttribute(gemm_s8,    cudaFuncAttributeMaxDynamicSharedMemorySize, SM_TOTAL);
    cudaFuncSetAttribute(mlp_tensor, cudaFuncAttributeMaxDynamicSharedMemorySize, M_SM);

    const size_t nadj = (size_t)NNODE * NNODE;              // 16.8M
    const size_t nx   = (size_t)BATCH * NNODE * NFEAT;      // 33.5M
    const dim3 ggrid(NNODE / 128, BATCH);                   // 32 x 64
    const int  nrows = BATCH * NNODE;                       // 262144

    // scales
    zero_scal<<<1, 1>>>(pS);
    rmax4<<<2048, 256>>>((const float4*)adj, (int)(nadj / 4), pS + 0);
    rmax4<<<2048, 256>>>((const float4*)x,   (int)(nx / 4),   pS + 1);

    // quantize inputs + weight prep
    quant1_pt<<<(unsigned)(nadj / (256 * 4)), 256>>>(adj, pA1, pS + 0);
    quant_xT<<<dim3(NNODE / 32, NFEAT / 32, BATCH), dim3(32, 8)>>>(x, pB1, pS + 1);
    wprep1<<<NHID * NFEAT / 256, 256>>>(W1, pW1);
    wprep2<<<NFEAT * NHID / 256, 256>>>(W2, pW2);

    // K1: Tb (bf16) = adj @ x
    gemm_s8<<<ggrid, 256, SM_TOTAL>>>(pA1, pB1, pTb, pS + 0, pS + 1,
                                      nullptr, nullptr);
    // K2: A2T = relu(Tb@W1+b1)@W2 (single-bf16 tensor-core), transposed + absmax
    mlp_tensor<<<nrows / 128, 256, M_SM>>>(pTb, pW1, pW2, b1, pM, pS + 2);
    // quantize MLP output (already [b][w][n])
    quant1_pt<<<(unsigned)(nx / (256 * 4)), 256>>>(pM, pB1, pS + 2);
    // K3 + fused bias/log_softmax -> out
    gemm_s8<<<ggrid, 256, SM_TOTAL>>>(pA1, pB1, nullptr, pS + 0, pS + 2,
                                      out, b2);

    (void)in_sizes; (void)n_in; (void)out_size;
}

// round 16
// speedup vs baseline: 2.6707x; 1.0570x over previous
#include <cuda_runtime.h>
#include <cuda_bf16.h>
#include <math.h>
#include <stdint.h>

// Problem dims (fixed by reference)
#define BATCH   64          // B*L
#define NNODE   4096        // H
#define NFEAT   128         // W == nclass
#define NHID    256

// ---------------------------------------------------------------------------
// Static device scratch (no allocations allowed)
// ---------------------------------------------------------------------------
__device__ int8_t g_A1 [(size_t)NNODE * NNODE];                  // adj int8 (per-row scale)
__device__ float  g_sA [NNODE];                                  // adj row absmax
__device__ int8_t g_B1 [(size_t)BATCH * NFEAT * NNODE];          // B int8 [b][w][k]
__device__ __nv_bfloat16 g_Tb [(size_t)BATCH * NNODE * NFEAT];   // GEMM1 out (bf16)
__device__ __nv_bfloat16 g_A2T[(size_t)BATCH * NFEAT * NNODE];   // MLP out transposed (bf16)
__device__ unsigned g_scal[3];                                   // absmax: (unused), x, mlp
__device__ __nv_bfloat16 g_W1T[NHID * NFEAT];                    // W1^T bf16 [256][128]
__device__ __nv_bfloat16 g_W2T[NFEAT * NHID];                    // W2^T bf16 [128][256]

// ---------------------------------------------------------------------------
// PTX helpers (sm_80-era: ldmatrix / mma.sync / cp.async)
// ---------------------------------------------------------------------------
__device__ __forceinline__ uint32_t smem_u32(const void* p) {
    uint32_t a;
    asm("{ .reg .u64 t; cvta.to.shared.u64 t, %1; cvt.u32.u64 %0, t; }" : "=r"(a) : "l"(p));
    return a;
}

#define LDSM4(r, a)                                                                 \
    asm volatile("ldmatrix.sync.aligned.m8n8.x4.shared.b16 {%0,%1,%2,%3}, [%4];"    \
        : "=r"((r)[0]), "=r"((r)[1]), "=r"((r)[2]), "=r"((r)[3]) : "r"(a))

#define LDSM2(r, a)                                                                 \
    asm volatile("ldmatrix.sync.aligned.m8n8.x2.shared.b16 {%0,%1}, [%2];"          \
        : "=r"((r)[0]), "=r"((r)[1]) : "r"(a))

#define MMA_S8(c, a, bb)                                                            \
    asm volatile("mma.sync.aligned.m16n8k32.row.col.s32.s8.s8.s32 "                 \
        "{%0,%1,%2,%3}, {%4,%5,%6,%7}, {%8,%9}, {%0,%1,%2,%3};"                     \
        : "+r"((c)[0]), "+r"((c)[1]), "+r"((c)[2]), "+r"((c)[3])                    \
        : "r"((a)[0]), "r"((a)[1]), "r"((a)[2]), "r"((a)[3]),                       \
          "r"((bb)[0]), "r"((bb)[1]))

#define MMA_BF16(c, a, bb)                                                          \
    asm volatile("mma.sync.aligned.m16n8k16.row.col.f32.bf16.bf16.f32 "             \
        "{%0,%1,%2,%3}, {%4,%5,%6,%7}, {%8,%9}, {%0,%1,%2,%3};"                     \
        : "+f"((c)[0]), "+f"((c)[1]), "+f"((c)[2]), "+f"((c)[3])                    \
        : "r"((a)[0]), "r"((a)[1]), "r"((a)[2]), "r"((a)[3]),                       \
          "r"((bb)[0]), "r"((bb)[1]))

#define CP16(dst, src) asm volatile("cp.async.cg.shared.global [%0], [%1], 16;" :: "r"(dst), "l"(src) : "memory")
#define CP_COMMIT()    asm volatile("cp.async.commit_group;" ::: "memory")
#define CP_WAIT1()     asm volatile("cp.async.wait_group 1;" ::: "memory")
#define CP_WAIT0()     asm volatile("cp.async.wait_group 0;" ::: "memory")

__device__ __forceinline__ int q1(float v, float inv) {
    return (int)fminf(127.f, fmaxf(-127.f, rintf(v * inv)));
}

__device__ __forceinline__ uint32_t packbf2(float a, float b) {
    return (uint32_t)__bfloat16_as_ushort(__float2bfloat16_rn(a)) |
           ((uint32_t)__bfloat16_as_ushort(__float2bfloat16_rn(b)) << 16);
}

// ---------------------------------------------------------------------------
// tiny kernels
// ---------------------------------------------------------------------------
__global__ void zero_scal(unsigned* s) { s[0] = 0u; s[1] = 0u; s[2] = 0u; }

__global__ void __launch_bounds__(256)
rmax4(const float4* __restrict__ p, int n4, unsigned* out)
{
    float m = 0.f;
    for (int i = blockIdx.x * blockDim.x + threadIdx.x; i < n4; i += gridDim.x * blockDim.x) {
        float4 v = p[i];
        m = fmaxf(m, fmaxf(fmaxf(fabsf(v.x), fabsf(v.y)), fmaxf(fabsf(v.z), fabsf(v.w))));
    }
    #pragma unroll
    for (int o = 16; o > 0; o >>= 1) m = fmaxf(m, __shfl_xor_sync(0xFFFFFFFFu, m, o));
    __shared__ float red[8];
    if ((threadIdx.x & 31) == 0) red[threadIdx.x >> 5] = m;
    __syncthreads();
    if (threadIdx.x == 0) {
        float b = red[0];
        #pragma unroll
        for (int i = 1; i < 8; i++) b = fmaxf(b, red[i]);
        atomicMax(out, __float_as_uint(b));
    }
}

// weight transpose + bf16 prep
__global__ void __launch_bounds__(256)
wprep1(const float* __restrict__ W1, __nv_bfloat16* __restrict__ h)
{
    int gid = blockIdx.x * 256 + threadIdx.x;           // 32768
    int r = gid >> 7, c = gid & 127;                    // out [256][128]
    h[gid] = __float2bfloat16_rn(W1[(size_t)c * NHID + r]);
}
__global__ void __launch_bounds__(256)
wprep2(const float* __restrict__ W2, __nv_bfloat16* __restrict__ h)
{
    int gid = blockIdx.x * 256 + threadIdx.x;           // 32768
    int r = gid >> 8, c = gid & 255;                    // out [128][256]
    h[gid] = __float2bfloat16_rn(W2[(size_t)c * NFEAT + r]);
}

// ---------------------------------------------------------------------------
// adj: fused per-row max + quantize. One block per row (4096 fp32).
// ---------------------------------------------------------------------------
__global__ void __launch_bounds__(256)
quant_adj_row(const float* __restrict__ adj, int8_t* __restrict__ d,
              float* __restrict__ rowmax)
{
    __shared__ float red[8];
    __shared__ float bmax;
    const int n = blockIdx.x, t = threadIdx.x;
    const float4* src = (const float4*)(adj + (size_t)n * NNODE) + t * 4;
    float4 v[4];
    float m = 0.f;
    #pragma unroll
    for (int i = 0; i < 4; i++) {
        v[i] = src[i];
        m = fmaxf(m, fmaxf(fmaxf(fabsf(v[i].x), fabsf(v[i].y)),
                           fmaxf(fabsf(v[i].z), fabsf(v[i].w))));
    }
    #pragma unroll
    for (int o = 16; o > 0; o >>= 1) m = fmaxf(m, __shfl_xor_sync(0xFFFFFFFFu, m, o));
    if ((t & 31) == 0) red[t >> 5] = m;
    __syncthreads();
    if (t == 0) {
        float b = red[0];
        #pragma unroll
        for (int i = 1; i < 8; i++) b = fmaxf(b, red[i]);
        bmax = b;
        rowmax[n] = b;
    }
    __syncthreads();
    const float inv = 127.f / fmaxf(bmax, 1e-30f);
    char o16[16];
    #pragma unroll
    for (int i = 0; i < 4; i++) {
        o16[i * 4 + 0] = (char)q1(v[i].x, inv);
        o16[i * 4 + 1] = (char)q1(v[i].y, inv);
        o16[i * 4 + 2] = (char)q1(v[i].z, inv);
        o16[i * 4 + 3] = (char)q1(v[i].w, inv);
    }
    *(uint4*)(d + (size_t)n * NNODE + t * 16) = *(uint4*)o16;
}

// ---------------------------------------------------------------------------
// x [b][n][w] fp32 -> int8 transposed [b][w][n] (global scale)
// ---------------------------------------------------------------------------
__global__ void __launch_bounds__(256)
quant_xT(const float* __restrict__ x, int8_t* __restrict__ d1,
         const unsigned* __restrict__ mx)
{
    __shared__ float t[32][33];
    const float inv = 127.f / fmaxf(__uint_as_float(*mx), 1e-30f);
    const int tx = threadIdx.x, ty = threadIdx.y;       // 32 x 8
    const int n0 = blockIdx.x * 32, w0 = blockIdx.y * 32, b = blockIdx.z;
    #pragma unroll
    for (int j = 0; j < 4; j++) {
        int n = n0 + ty + j * 8;
        t[ty + j * 8][tx] = x[((size_t)b * NNODE + n) * NFEAT + w0 + tx];
    }
    __syncthreads();
    #pragma unroll
    for (int j = 0; j < 4; j++) {
        int w = w0 + ty + j * 8;
        size_t o = ((size_t)b * NFEAT + w) * NNODE + n0 + tx;
        d1[o] = (int8_t)q1(t[tx][ty + j * 8], inv);
    }
}

// ---------------------------------------------------------------------------
// bf16 -> int8 quantize (MLP output, already [b][w][n], global scale)
// ---------------------------------------------------------------------------
__global__ void __launch_bounds__(256)
quant1_bf(const __nv_bfloat16* __restrict__ src, int8_t* __restrict__ d1,
          const unsigned* __restrict__ mx)
{
    const float inv = 127.f / fmaxf(__uint_as_float(*mx), 1e-30f);
    const size_t i = ((size_t)blockIdx.x * 256 + threadIdx.x) * 8;
    uint4 raw = *(const uint4*)(src + i);
    const __nv_bfloat16* h = (const __nv_bfloat16*)&raw;
    char o8[8];
    #pragma unroll
    for (int j = 0; j < 8; j++) o8[j] = (char)q1(__bfloat162float(h[j]), inv);
    *(uint2*)(d1 + i) = *(uint2*)o8;
}

// ---------------------------------------------------------------------------
// int8 GEMM: C[b][n][w] = sA[n]/127 * mB/127 * sum_k a1[n,k]*b1[w,k]
// A per-row scale (sArow), B global scale (maxB).
// GEMM1 mode (out2==null): bf16 C out. GEMM2 mode: fused bias+log_softmax.
// 256 thr, warp tile 64x32, B fragments via ldmatrix.x4 (2 n-groups/instr).
// ---------------------------------------------------------------------------
#define KC       128
#define NSTAGE   (NNODE / KC)              // 32
#define ROW_B    144
#define TILE_B   (128 * ROW_B)             // 18432
#define STAGE_B  (2 * TILE_B)              // 36864  (A1, B1)
#define SM_TOTAL (2 * STAGE_B)             // 73728

__global__ void __launch_bounds__(256, 2)
gemm_s8(const int8_t* __restrict__ A1, const int8_t* __restrict__ B1,
        __nv_bfloat16* __restrict__ Cb16,
        const float* __restrict__ sArow, const unsigned* __restrict__ maxB,
        float* __restrict__ out2, const float* __restrict__ bias2)
{
    extern __shared__ __align__(16) char smem[];
    const uint32_t sb = smem_u32(smem);
    const int tid  = threadIdx.x;
    const int wid  = tid >> 5, lane = tid & 31;
    const int wm   = wid & 1;
    const int wn   = wid >> 1;
    const int n0 = blockIdx.x * 128, b = blockIdx.y;

    const int8_t* tb[2] = {
        A1 + (size_t)n0 * NNODE,
        B1 + (size_t)b * NFEAT * NNODE };

    const int c16   = (tid & 7) * 16;
    const int rbase = tid >> 3;            // 0..31

    const uint32_t offA  = (uint32_t)(wm * 64 + (lane & 15)) * ROW_B + (lane >> 4) * 16;
    // x4 B address: lanes 0-15 -> n-group g, lanes 16-31 -> group g+1
    const uint32_t offB4 = (uint32_t)(wn * 32 + ((lane >> 4) << 3) + (lane & 7)) * ROW_B
                         + ((lane >> 3) & 1) * 16;

    int p1[4][4][4];
    #pragma unroll
    for (int mi = 0; mi < 4; mi++)
        #pragma unroll
        for (int ni = 0; ni < 4; ni++)
            #pragma unroll
            for (int e = 0; e < 4; e++) p1[mi][ni][e] = 0;

    #pragma unroll
    for (int j = 0; j < 8; j++) {
        const int row = (j & 3) * 32 + rbase;
        CP16(sb + (j >> 2) * TILE_B + row * ROW_B + c16,
             tb[j >> 2] + (size_t)row * NNODE + c16);
    }
    CP_COMMIT();

    for (int i = 0; i < NSTAGE; i++) {
        const int buf = i & 1;
        if (i < NSTAGE - 1) {
            const uint32_t dbase = sb + (buf ^ 1) * STAGE_B;
            const int koff = (i + 1) * KC;
            #pragma unroll
            for (int j = 0; j < 8; j++) {
                const int row = (j & 3) * 32 + rbase;
                CP16(dbase + (j >> 2) * TILE_B + row * ROW_B + c16,
                     tb[j >> 2] + (size_t)row * NNODE + koff + c16);
            }
            CP_COMMIT();
            CP_WAIT1();
        } else {
            CP_WAIT0();
        }
        __syncthreads();

        const uint32_t s = sb + buf * STAGE_B;
        #pragma unroll
        for (int ks = 0; ks < 4; ks++) {
            uint32_t a1f[4][4];
            #pragma unroll
            for (int mi = 0; mi < 4; mi++)
                LDSM4(a1f[mi], s + offA + mi * (16 * ROW_B) + ks * 32);
            #pragma unroll
            for (int ni = 0; ni < 4; ni += 2) {
                uint32_t b4[4];   // [0..1] = group ni, [2..3] = group ni+1
                LDSM4(b4, s + TILE_B + offB4 + ni * (8 * ROW_B) + ks * 32);
                #pragma unroll
                for (int mi = 0; mi < 4; mi++) {
                    MMA_S8(p1[mi][ni],     a1f[mi], (b4));
                    MMA_S8(p1[mi][ni + 1], a1f[mi], (b4 + 2));
                }
            }
        }
        __syncthreads();
    }

    const float f = __uint_as_float(*maxB) * (1.f / 16129.f);   // mB/127^2
    const int mrow = wm * 64 + (lane >> 2);
    const int ncol = wn * 32 + (lane & 3) * 2;

    if (out2 == nullptr) {
        __nv_bfloat16* Cb = Cb16 + ((size_t)b * NNODE + n0) * NFEAT;
        #pragma unroll
        for (int mi = 0; mi < 4; mi++) {
            const float s0 = sArow[n0 + mrow + mi * 16] * f;
            const float s1 = sArow[n0 + mrow + mi * 16 + 8] * f;
            #pragma unroll
            for (int ni = 0; ni < 4; ni++) {
                const size_t i0 = (size_t)(mrow + mi * 16) * NFEAT + ncol + ni * 8;
                *(uint32_t*)(Cb + i0) =
                    packbf2(s0 * (float)p1[mi][ni][0], s0 * (float)p1[mi][ni][1]);
                *(uint32_t*)(Cb + i0 + 8 * NFEAT) =
                    packbf2(s1 * (float)p1[mi][ni][2], s1 * (float)p1[mi][ni][3]);
            }
        }
    } else {
        // fused bias + log_softmax epilogue: bounce acc through smem (stages dead)
        float* sm = (float*)smem;                       // [128][132] fp32
        #pragma unroll
        for (int mi = 0; mi < 4; mi++) {
            const float s0 = sArow[n0 + mrow + mi * 16] * f;
            const float s1 = sArow[n0 + mrow + mi * 16 + 8] * f;
            #pragma unroll
            for (int ni = 0; ni < 4; ni++) {
                const int r0 = mrow + mi * 16, c0 = ncol + ni * 8;
                sm[r0 * 132 + c0]           = s0 * (float)p1[mi][ni][0];
                sm[r0 * 132 + c0 + 1]       = s0 * (float)p1[mi][ni][1];
                sm[(r0 + 8) * 132 + c0]     = s1 * (float)p1[mi][ni][2];
                sm[(r0 + 8) * 132 + c0 + 1] = s1 * (float)p1[mi][ni][3];
            }
        }
        __syncthreads();
        const float4 bb = ((const float4*)bias2)[lane];
        for (int rr = wid * 16; rr < wid * 16 + 16; rr++) {
            float4 v = *(float4*)&sm[rr * 132 + lane * 4];
            float v0 = v.x + bb.x, v1 = v.y + bb.y, v2 = v.z + bb.z, v3 = v.w + bb.w;
            float m = fmaxf(fmaxf(v0, v1), fmaxf(v2, v3));
            #pragma unroll
            for (int o = 16; o > 0; o >>= 1) m = fmaxf(m, __shfl_xor_sync(0xFFFFFFFFu, m, o));
            float ss = expf(v0 - m) + expf(v1 - m) + expf(v2 - m) + expf(v3 - m);
            #pragma unroll
            for (int o = 16; o > 0; o >>= 1) ss += __shfl_xor_sync(0xFFFFFFFFu, ss, o);
            const float lse = m + logf(ss);
            float4 o4; o4.x = v0 - lse; o4.y = v1 - lse; o4.z = v2 - lse; o4.w = v3 - lse;
            *(float4*)(out2 + ((size_t)b * NNODE + n0 + rr) * NFEAT + lane * 4) = o4;
        }
    }
}

// ---------------------------------------------------------------------------
// MLP on tensor cores — single bf16. Per CTA: 128 rows.
// A2T[b][w][n] (bf16) = relu(T @ W1 + b1) @ W2, + global absmax.
// ---------------------------------------------------------------------------
#define MROWB 272                                      // 256B data + 16 pad
#define MTILE (128 * MROWB)                            // 34816
#define M_RA  0
#define M_RB  MTILE
#define M_RC  (2 * MTILE)
#define M_SM  (3 * MTILE)                              // 104448

__global__ void __launch_bounds__(256, 1)
mlp_tensor(const __nv_bfloat16* __restrict__ Tb,
           const __nv_bfloat16* __restrict__ W1T,
           const __nv_bfloat16* __restrict__ W2T,
           const float* __restrict__ b1,
           __nv_bfloat16* __restrict__ A2T, unsigned* __restrict__ mx)
{
    extern __shared__ __align__(16) char smem[];
    const uint32_t sb = smem_u32(smem);
    const int tid  = threadIdx.x;
    const int wid  = tid >> 5, lane = tid & 31;
    const int wm   = wid & 1, wn = wid >> 1;
    const size_t row0 = (size_t)blockIdx.x * 128;
    const int b     = (int)(row0 >> 12);
    const int nbase = (int)(row0 & 4095);

    // --- load T rows + W1T half0 ---
    #pragma unroll
    for (int j = 0; j < 8; j++) {
        int cid = j * 256 + tid;
        int r = cid >> 4, c = cid & 15;
        CP16(sb + M_RA + r * MROWB + c * 16, Tb + (row0 + r) * NFEAT + c * 8);
        CP16(sb + M_RB + r * MROWB + c * 16, W1T + (size_t)r * NFEAT + c * 8);
    }
    CP_COMMIT();
    CP_WAIT0();
    __syncthreads();

    const uint32_t offA = (uint32_t)(wm * 64 + (lane & 15)) * MROWB + (lane >> 4) * 16;
    const uint32_t offB = (uint32_t)(wn * 32 + (lane & 7)) * MROWB + ((lane >> 3) & 1) * 16;

    float acc2[4][4][4];
    #pragma unroll
    for (int mi = 0; mi < 4; mi++)
        #pragma unroll
        for (int ni = 0; ni < 4; ni++)
            #pragma unroll
            for (int e = 0; e < 4; e++) acc2[mi][ni][e] = 0.f;

    #pragma unroll 1
    for (int half = 0; half < 2; half++) {
        float acc1[4][4][4];
        #pragma unroll
        for (int mi = 0; mi < 4; mi++)
            #pragma unroll
            for (int ni = 0; ni < 4; ni++)
                #pragma unroll
                for (int e = 0; e < 4; e++) acc1[mi][ni][e] = 0.f;

        #pragma unroll
        for (int ks = 0; ks < 8; ks++) {
            uint32_t ah[4][4];
            #pragma unroll
            for (int mi = 0; mi < 4; mi++)
                LDSM4(ah[mi], sb + M_RA + offA + mi * (16 * MROWB) + ks * 32);
            #pragma unroll
            for (int ni = 0; ni < 4; ni++) {
                uint32_t bh[2];
                LDSM2(bh, sb + M_RB + offB + ni * (8 * MROWB) + ks * 32);
                #pragma unroll
                for (int mi = 0; mi < 4; mi++)
                    MMA_BF16(acc1[mi][ni], ah[mi], bh);
            }
        }
        __syncthreads();

        // load W2T half into RB
        #pragma unroll
        for (int j = 0; j < 8; j++) {
            int cid = j * 256 + tid;
            int r = cid >> 4, c = cid & 15;
            CP16(sb + M_RB + r * MROWB + c * 16,
                 W2T + (size_t)r * NHID + half * 128 + c * 8);
        }
        CP_COMMIT();

        // relu + bias + bf16 h -> RC
        {
            const int cb = wn * 32 + (lane & 3) * 2;
            #pragma unroll
            for (int ni = 0; ni < 4; ni++) {
                const float2 bv = *(const float2*)(b1 + half * 128 + cb + ni * 8);
                #pragma unroll
                for (int mi = 0; mi < 4; mi++) {
                    const int r = wm * 64 + (lane >> 2) + mi * 16;
                    const uint32_t c2 = (cb + ni * 8) * 2;
                    uint32_t v0 = packbf2(fmaxf(acc1[mi][ni][0] + bv.x, 0.f),
                                          fmaxf(acc1[mi][ni][1] + bv.y, 0.f));
                    uint32_t v1 = packbf2(fmaxf(acc1[mi][ni][2] + bv.x, 0.f),
                                          fmaxf(acc1[mi][ni][3] + bv.y, 0.f));
                    asm volatile("st.shared.u32 [%0], %1;"
                                 :: "r"(sb + M_RC + r * MROWB + c2), "r"(v0));
                    asm volatile("st.shared.u32 [%0], %1;"
                                 :: "r"(sb + M_RC + (r + 8) * MROWB + c2), "r"(v1));
                }
            }
        }
        CP_WAIT0();
        __syncthreads();

        // layer 2 half
        #pragma unroll
        for (int ks = 0; ks < 8; ks++) {
            uint32_t ah[4][4];
            #pragma unroll
            for (int mi = 0; mi < 4; mi++)
                LDSM4(ah[mi], sb + M_RC + offA + mi * (16 * MROWB) + ks * 32);
            #pragma unroll
            for (int ni = 0; ni < 4; ni++) {
                uint32_t bh[2];
                LDSM2(bh, sb + M_RB + offB + ni * (8 * MROWB) + ks * 32);
                #pragma unroll
                for (int mi = 0; mi < 4; mi++)
                    MMA_BF16(acc2[mi][ni], ah[mi], bh);
            }
        }
        if (half == 0) {
            __syncthreads();
            #pragma unroll
            for (int j = 0; j < 8; j++) {
                int cid = j * 256 + tid;
                int r = cid >> 4, c = cid & 15;
                CP16(sb + M_RB + r * MROWB + c * 16,
                     W1T + (size_t)(128 + r) * NFEAT + c * 8);
            }
            CP_COMMIT();
            CP_WAIT0();
            __syncthreads();
        }
    }

    // ---- epilogue: transpose via smem, write bf16 A2T + absmax ----
    __syncthreads();
    float* sm = (float*)smem;                // [128][132] fp32
    {
        const int mrow = wm * 64 + (lane >> 2);
        const int ncol = wn * 32 + (lane & 3) * 2;
        #pragma unroll
        for (int mi = 0; mi < 4; mi++)
            #pragma unroll
            for (int ni = 0; ni < 4; ni++) {
                const int r0 = mrow + mi * 16, c0 = ncol + ni * 8;
                sm[r0 * 132 + c0]           = acc2[mi][ni][0];
                sm[r0 * 132 + c0 + 1]       = acc2[mi][ni][1];
                sm[(r0 + 8) * 132 + c0]     = acc2[mi][ni][2];
                sm[(r0 + 8) * 132 + c0 + 1] = acc2[mi][ni][3];
            }
    }
    __syncthreads();
    {
        const int w  = tid & 127;
        const int nh = (tid >> 7) * 64;
        float lm = 0.f;
        __nv_bfloat16* dst = A2T + ((size_t)b * NFEAT + w) * NNODE + nbase + nh;
        #pragma unroll
        for (int g = 0; g < 16; g++) {
            float a = sm[(nh + g * 4 + 0) * 132 + w];
            float bq = sm[(nh + g * 4 + 1) * 132 + w];
            float cq = sm[(nh + g * 4 + 2) * 132 + w];
            float dq = sm[(nh + g * 4 + 3) * 132 + w];
            lm = fmaxf(lm, fmaxf(fmaxf(fabsf(a), fabsf(bq)), fmaxf(fabsf(cq), fabsf(dq))));
            uint2 pk;
            pk.x = packbf2(a, bq);
            pk.y = packbf2(cq, dq);
            *(uint2*)(dst + g * 4) = pk;
        }
        #pragma unroll
        for (int o = 16; o > 0; o >>= 1) lm = fmaxf(lm, __shfl_xor_sync(0xFFFFFFFFu, lm, o));
        __shared__ float red[8];
        if ((tid & 31) == 0) red[tid >> 5] = lm;
        __syncthreads();
        if (tid == 0) {
            float bm = red[0];
            #pragma unroll
            for (int i = 1; i < 8; i++) bm = fmaxf(bm, red[i]);
            atomicMax(mx, __float_as_uint(bm));
        }
    }
}

// ---------------------------------------------------------------------------
// Launch sequence
// ---------------------------------------------------------------------------
extern "C" void kernel_launch(void* const* d_in, const int* in_sizes, int n_in,
                              void* d_out, int out_size)
{
    const float* x   = (const float*)d_in[0];
    const float* adj = (const float*)d_in[1];
    const float* W1  = (const float*)d_in[2];
    const float* b1  = (const float*)d_in[3];
    const float* W2  = (const float*)d_in[4];
    const float* b2  = (const float*)d_in[5];
    float* out = (float*)d_out;

    int8_t *pA1, *pB1; float* pSA; unsigned* pS;
    __nv_bfloat16 *pTb, *pM, *pW1, *pW2;
    cudaGetSymbolAddress((void**)&pA1, g_A1);
    cudaGetSymbolAddress((void**)&pB1, g_B1);
    cudaGetSymbolAddress((void**)&pSA, g_sA);
    cudaGetSymbolAddress((void**)&pTb, g_Tb);
    cudaGetSymbolAddress((void**)&pM,  g_A2T);
    cudaGetSymbolAddress((void**)&pS,  g_scal);
    cudaGetSymbolAddress((void**)&pW1, g_W1T);
    cudaGetSymbolAddress((void**)&pW2, g_W2T);

    cudaFuncSetAttribute(gemm_s8,    cudaFuncAttributeMaxDynamicSharedMemorySize, SM_TOTAL);
    cudaFuncSetAttribute(mlp_tensor, cudaFuncAttributeMaxDynamicSharedMemorySize, M_SM);

    const size_t nx = (size_t)BATCH * NNODE * NFEAT;        // 33.5M
    const dim3 ggrid(NNODE / 128, BATCH);                   // 32 x 64
    const int  nrows = BATCH * NNODE;                       // 262144

    // scales
    zero_scal<<<1, 1>>>(pS);
    rmax4<<<2048, 256>>>((const float4*)x, (int)(nx / 4), pS + 1);

    // quantize inputs + weight prep
    quant_adj_row<<<NNODE, 256>>>(adj, pA1, pSA);
    quant_xT<<<dim3(NNODE / 32, NFEAT / 32, BATCH), dim3(32, 8)>>>(x, pB1, pS + 1);
    wprep1<<<NHID * NFEAT / 256, 256>>>(W1, pW1);
    wprep2<<<NFEAT * NHID / 256, 256>>>(W2, pW2);

    // K1: Tb (bf16) = adj @ x
    gemm_s8<<<ggrid, 256, SM_TOTAL>>>(pA1, pB1, pTb, pSA, pS + 1,
                                      nullptr, nullptr);
    // K2: A2T (bf16) = relu(Tb@W1+b1)@W2, transposed + absmax
    mlp_tensor<<<nrows / 128, 256, M_SM>>>(pTb, pW1, pW2, b1, pM, pS + 2);
    // quantize MLP output (bf16 -> int8, already [b][w][n])
    quant1_bf<<<(unsigned)(nx / (256 * 8)), 256>>>(pM, pB1, pS + 2);
    // K3 + fused bias/log_softmax -> out
    gemm_s8<<<ggrid, 256, SM_TOTAL>>>(pA1, pB1, nullptr, pSA, pS + 2,
                                      out, b2);

    (void)in_sizes; (void)n_in; (void)out_size;
}